// round 9
// baseline (speedup 1.0000x reference)
#include <cuda_runtime.h>
#include <cuda_bf16.h>
#include <cstdint>

// Problem constants
#define B_   2
#define T_   1024
#define CH_  1024
#define H_   16
#define KC_  64
#define WIN_ 4
#define MROWS (B_ * T_)          // 2048
#define BHT  (B_ * H_ * T_)      // 32768

// ---------------- scratch (static device globals; no allocation) ----------------
__device__ __nv_bfloat16 g_q_hi[BHT * KC_];
__device__ __nv_bfloat16 g_q_lo[BHT * KC_];
__device__ __nv_bfloat16 g_k_hi[BHT * KC_];
__device__ __nv_bfloat16 g_k_lo[BHT * KC_];
__device__ __nv_bfloat16 g_v_hi[BHT * KC_];
__device__ __nv_bfloat16 g_v_lo[BHT * KC_];

__device__ __nv_bfloat16 gx_hi[MROWS * CH_];
__device__ __nv_bfloat16 gx_lo[MROWS * CH_];
__device__ __nv_bfloat16 gc_hi[MROWS * CH_];
__device__ __nv_bfloat16 gc_lo[MROWS * CH_];
__device__ __nv_bfloat16 gw_hi[4 * CH_ * CH_];   // W^T concat [q|k|v|o]
__device__ __nv_bfloat16 gw_lo[4 * CH_ * CH_];
__device__ __nv_bfloat16 g_att_hi[MROWS * CH_];
__device__ __nv_bfloat16 g_att_lo[MROWS * CH_];
__device__ float g_bias[4 * CH_];
__device__ uint32_t g_mbits[MROWS * (T_ / 32)];

// ======================= helpers ================================================
__device__ __forceinline__ void mma16816(float* c, const uint32_t* a, const uint32_t* b)
{
    asm volatile(
        "mma.sync.aligned.m16n8k16.row.col.f32.bf16.bf16.f32 "
        "{%0,%1,%2,%3}, {%4,%5,%6,%7}, {%8,%9}, {%0,%1,%2,%3};"
        : "+f"(c[0]), "+f"(c[1]), "+f"(c[2]), "+f"(c[3])
        : "r"(a[0]), "r"(a[1]), "r"(a[2]), "r"(a[3]), "r"(b[0]), "r"(b[1]));
}

__device__ __forceinline__ void ldm_x4(uint32_t* r, uint32_t addr)
{
    asm volatile(
        "ldmatrix.sync.aligned.m8n8.x4.shared.b16 {%0,%1,%2,%3}, [%4];"
        : "=r"(r[0]), "=r"(r[1]), "=r"(r[2]), "=r"(r[3]) : "r"(addr));
}

__device__ __forceinline__ void splitbf(float x, __nv_bfloat16& h, __nv_bfloat16& l)
{
    h = __float2bfloat16_rn(x);
    l = __float2bfloat16_rn(x - __bfloat162float(h));
}

__device__ __forceinline__ void split_pack(float x, float y, uint32_t& hi, uint32_t& lo)
{
    __nv_bfloat16 hx, lx, hy, ly;
    splitbf(x, hx, lx); splitbf(y, hy, ly);
    __nv_bfloat162 th = __halves2bfloat162(hx, hy);
    __nv_bfloat162 tl = __halves2bfloat162(lx, ly);
    hi = *reinterpret_cast<uint32_t*>(&th);
    lo = *reinterpret_cast<uint32_t*>(&tl);
}

__device__ __forceinline__ uint32_t smem_u32(const void* p) {
    uint32_t a;
    asm("{ .reg .u64 t; cvta.to.shared.u64 t, %1; cvt.u32.u64 %0, t; }"
        : "=r"(a) : "l"(p));
    return a;
}

__device__ __forceinline__ void cpa16(uint32_t dst, const void* src) {
    asm volatile("cp.async.cg.shared.global [%0], [%1], 16;" :: "r"(dst), "l"(src));
}

// ======================= prep kernels ==========================================
__global__ __launch_bounds__(256) void conv_in(
    const float* __restrict__ x, const float* __restrict__ c,
    const float* __restrict__ bq, const float* __restrict__ bk,
    const float* __restrict__ bv, const float* __restrict__ bo)
{
    int i = blockIdx.x * 256 + threadIdx.x;
    const float4* src;
    __nv_bfloat162 *dh, *dl;
    int j;
    if (i < 524288) {
        src = (const float4*)x; j = i;
        dh = (__nv_bfloat162*)gx_hi; dl = (__nv_bfloat162*)gx_lo;
    } else {
        src = (const float4*)c; j = i - 524288;
        dh = (__nv_bfloat162*)gc_hi; dl = (__nv_bfloat162*)gc_lo;
    }
    float4 v = src[j];
    __nv_bfloat16 hx, lx, hy, ly, hz, lz, hw, lw;
    splitbf(v.x, hx, lx); splitbf(v.y, hy, ly);
    splitbf(v.z, hz, lz); splitbf(v.w, hw, lw);
    dh[2 * j]     = __halves2bfloat162(hx, hy);
    dh[2 * j + 1] = __halves2bfloat162(hz, hw);
    dl[2 * j]     = __halves2bfloat162(lx, ly);
    dl[2 * j + 1] = __halves2bfloat162(lz, lw);
    if (i < 4096) {
        float b = (i < 1024) ? bq[i] : (i < 2048) ? bk[i - 1024]
                : (i < 3072) ? bv[i - 2048] : bo[i - 3072];
        g_bias[i] = b;
    }
}

__global__ __launch_bounds__(256) void conv_w(
    const float* __restrict__ Wq, const float* __restrict__ Wk,
    const float* __restrict__ Wv, const float* __restrict__ Wo)
{
    __shared__ float tile[32][33];
    int z = blockIdx.z;
    const float* W = (z == 0) ? Wq : (z == 1) ? Wk : (z == 2) ? Wv : Wo;
    int n0 = blockIdx.x * 32, k0 = blockIdx.y * 32;
    int tx = threadIdx.x & 31, ty = threadIdx.x >> 5;
#pragma unroll
    for (int u = 0; u < 4; ++u) {
        int k = k0 + ty + u * 8;
        tile[ty + u * 8][tx] = W[k * 1024 + n0 + tx];
    }
    __syncthreads();
#pragma unroll
    for (int u = 0; u < 4; ++u) {
        int r = ty + u * 8;
        float v = tile[tx][r];
        int dst = (z * 1024 + n0 + r) * 1024 + k0 + tx;
        __nv_bfloat16 h, l;
        splitbf(v, h, l);
        gw_hi[dst] = h;
        gw_lo[dst] = l;
    }
}

__global__ __launch_bounds__(256) void mask_pack(const int* __restrict__ mask)
{
    int idx = blockIdx.x * 256 + threadIdx.x;
    uint32_t bits = __ballot_sync(0xffffffffu, mask[idx] != 0);
    if ((threadIdx.x & 31) == 0) g_mbits[idx >> 5] = bits;
}

// ======================= cp.async double-buffered bf16-split GEMM ==============
// 512 threads, 4x4 warp grid, 32x32 warp tiles (16 warps to hide HMMA latency)
#define LDK 72                        // padded k-stride (bf16), 144B rows
#define TILE_B (128 * LDK * 2)        // 18432 B
#define STAGE_B (4 * TILE_B)          // 73728 B
#define GEMM_SMEM (2 * STAGE_B)       // 147456 B
__global__ __launch_bounds__(512, 1) void gemm_mma(int mode, float* __restrict__ finalout)
{
    extern __shared__ __nv_bfloat16 sm[];
    uint32_t sbase = smem_u32(sm);

    int tid = threadIdx.x;
    int wid = tid >> 5, lane = tid & 31;
    int g = lane >> 2, tg = lane & 3;
    int warp_m = wid & 3, warp_n = wid >> 2;   // 4x4 warps; 32x32 tiles
    int z = (mode == 0) ? (int)blockIdx.z : 3;

    const __nv_bfloat16 *A_hi, *A_lo;
    if (mode == 0) {
        if (z == 0) { A_hi = gx_hi; A_lo = gx_lo; }
        else        { A_hi = gc_hi; A_lo = gc_lo; }
    } else { A_hi = g_att_hi; A_lo = g_att_lo; }
    int arow0 = blockIdx.y * 128;
    int brow0 = z * 1024 + blockIdx.x * 128;

    auto issue_stage = [&](int stage, int k0) {
        const __nv_bfloat16* srcs[4] = {A_hi, A_lo, gw_hi, gw_lo};
        int rows0[4] = {arow0, arow0, brow0, brow0};
        uint32_t stoff = sbase + (uint32_t)stage * STAGE_B;
#pragma unroll
        for (int arr = 0; arr < 4; ++arr) {
#pragma unroll
            for (int u = 0; u < 2; ++u) {
                int lin = tid + u * 512;          // 0..1023
                int r = lin >> 3, c8 = lin & 7;
                cpa16(stoff + (uint32_t)arr * TILE_B + r * 144 + c8 * 16,
                      srcs[arr] + (size_t)(rows0[arr] + r) * 1024 + k0 + c8 * 8);
            }
        }
        asm volatile("cp.async.commit_group;" ::: "memory");
    };

    float acc[2][4][4];
#pragma unroll
    for (int mi = 0; mi < 2; ++mi)
#pragma unroll
        for (int ni = 0; ni < 4; ++ni)
#pragma unroll
            for (int e = 0; e < 4; ++e) acc[mi][ni][e] = 0.f;

    // ldmatrix per-thread offsets
    uint32_t a_off = (uint32_t)((warp_m * 32 + (lane & 15)) * 144 + ((lane >> 4) << 4));
    uint32_t b_off = (uint32_t)((warp_n * 32 + (((lane >> 4) & 1) << 3) + (lane & 7)) * 144
                                + (((lane >> 3) & 1) << 4));

    issue_stage(0, 0);

    for (int s = 0; s < 16; ++s) {
        asm volatile("cp.async.wait_group 0;" ::: "memory");
        __syncthreads();
        if (s + 1 < 16) issue_stage((s + 1) & 1, (s + 1) * 64);

        uint32_t stb = sbase + (uint32_t)(s & 1) * STAGE_B;
        uint32_t aHb = stb, aLb = stb + TILE_B, bHb = stb + 2 * TILE_B, bLb = stb + 3 * TILE_B;

#pragma unroll
        for (int kk = 0; kk < 4; ++kk) {
            uint32_t kb = (uint32_t)kk * 32;
            uint32_t ah[2][4], al[2][4], bh[2][4], bl[2][4];
#pragma unroll
            for (int mi = 0; mi < 2; ++mi) {
                ldm_x4(ah[mi], aHb + a_off + (uint32_t)mi * (16 * 144) + kb);
                ldm_x4(al[mi], aLb + a_off + (uint32_t)mi * (16 * 144) + kb);
            }
#pragma unroll
            for (int p = 0; p < 2; ++p) {
                ldm_x4(bh[p], bHb + b_off + (uint32_t)p * (16 * 144) + kb);
                ldm_x4(bl[p], bLb + b_off + (uint32_t)p * (16 * 144) + kb);
            }
#pragma unroll
            for (int mi = 0; mi < 2; ++mi)
#pragma unroll
                for (int ni = 0; ni < 4; ++ni) {
                    const uint32_t* bhf = &bh[ni >> 1][(ni & 1) * 2];
                    const uint32_t* blf = &bl[ni >> 1][(ni & 1) * 2];
                    mma16816(acc[mi][ni], ah[mi], bhf);
                    mma16816(acc[mi][ni], ah[mi], blf);
                    mma16816(acc[mi][ni], al[mi], bhf);
                }
        }
    }

    float scale = (mode == 0 && z == 0) ? 0.125f : 1.0f;
    __nv_bfloat16* dsth = (z == 0) ? g_q_hi : (z == 1) ? g_k_hi : g_v_hi;
    __nv_bfloat16* dstl = (z == 0) ? g_q_lo : (z == 1) ? g_k_lo : g_v_lo;
#pragma unroll
    for (int mi = 0; mi < 2; ++mi) {
#pragma unroll
        for (int ni = 0; ni < 4; ++ni) {
#pragma unroll
            for (int e = 0; e < 4; ++e) {
                int row = blockIdx.y * 128 + warp_m * 32 + mi * 16 + g + ((e >> 1) ? 8 : 0);
                int col = blockIdx.x * 128 + warp_n * 32 + ni * 8 + 2 * tg + (e & 1);
                float v = (acc[mi][ni][e] + g_bias[z * 1024 + col]) * scale;
                if (mode == 0) {
                    int h = col >> 6, bb = row >> 10, t = row & 1023, d = col & 63;
                    int idx = (((bb * 16 + h) << 16) | (t << 6)) + d;
                    __nv_bfloat16 hh, ll;
                    splitbf(v, hh, ll);
                    dsth[idx] = hh;
                    dstl[idx] = ll;
                } else {
                    finalout[(size_t)row * 1024 + col] = v;
                }
            }
        }
    }
}

// =================== fused flash attention ======================================
// grid (8, 32), 256 threads, 2 CTAs/SM. i-tile=128, j-tile=64.
#define ATT_SMEM 89088
__global__ __launch_bounds__(256, 2) void attn_fused(
    const float* __restrict__ erv, const float* __restrict__ erk)
{
    extern __shared__ char smc[];
    __nv_bfloat16 (*QH)[72]  = (__nv_bfloat16(*)[72])(smc);
    __nv_bfloat16 (*QL)[72]  = (__nv_bfloat16(*)[72])(smc + 18432);
    __nv_bfloat16 (*KH)[72]  = (__nv_bfloat16(*)[72])(smc + 36864);
    __nv_bfloat16 (*KL)[72]  = (__nv_bfloat16(*)[72])(smc + 46080);
    __nv_bfloat16 (*VTH)[72] = (__nv_bfloat16(*)[72])(smc + 55296);
    __nv_bfloat16 (*VTL)[72] = (__nv_bfloat16(*)[72])(smc + 64512);
    float (*BAND)[12] = (float(*)[12])(smc + 73728);
    float (*RLS)[9]   = (float(*)[9])(smc + 79872);
    float* ERVS       = (float*)(smc + 84480);
    float* ERKS       = (float*)(smc + 86784);

    uint32_t sb = smem_u32(smc);
    const uint32_t QH_a = sb, QL_a = sb + 18432, KH_a = sb + 36864, KL_a = sb + 46080;
    const uint32_t VTH_a = sb + 55296, VTL_a = sb + 64512;

    int tid = threadIdx.x, wid = tid >> 5, lane = tid & 31;
    int g = lane >> 2, tq = lane & 3;
    int bh = blockIdx.y, b = bh >> 4, h = bh & 15;
    int i0 = blockIdx.x * 128;

    uint32_t q_off = (uint32_t)((wid * 16 + (lane & 15)) * 144 + ((lane >> 4) << 4));
    uint32_t k_off = (uint32_t)(((((lane >> 4) & 1) << 3) + (lane & 7)) * 144
                                + (((lane >> 3) & 1) << 4));

#pragma unroll
    for (int u = 0; u < 4; ++u) {
        int lin = tid + u * 256;
        int r = lin >> 3, c8 = lin & 7;
        const size_t go = (size_t)(bh * 1024 + i0 + r) * 64 + c8 * 8;
        *(uint4*)&QH[r][c8 * 8] = *(const uint4*)(g_q_hi + go);
        *(uint4*)&QL[r][c8 * 8] = *(const uint4*)(g_q_lo + go);
    }
    for (int idx = tid; idx < 576; idx += 256) { ERVS[idx] = erv[idx]; ERKS[idx] = erk[idx]; }
    for (int idx = tid; idx < 128 * 12; idx += 256) ((float*)BAND)[idx] = 0.f;
    __syncthreads();

    for (int idx = tid; idx < 1152; idx += 256) {
        int r = idx / 9, u = idx - r * 9;
        float s = 0.f;
        const float* e = ERKS + u * 64;
#pragma unroll
        for (int d = 0; d < 64; ++d)
            s += (__bfloat162float(QH[r][d]) + __bfloat162float(QL[r][d])) * e[d];
        RLS[r][u] = s;
    }

    float O[8][4];
#pragma unroll
    for (int nd = 0; nd < 8; ++nd)
#pragma unroll
        for (int e = 0; e < 4; ++e) O[nd][e] = 0.f;
    float m0 = -1e30f, m1 = -1e30f, l0 = 0.f, l1 = 0.f;

    const int rbase = wid * 16 + g;
    const uint32_t* mrow0 = g_mbits + ((size_t)(b << 10) + i0 + rbase) * 32;
    const uint32_t* mrow1 = mrow0 + 8 * 32;

    for (int jt = 0; jt < 16; ++jt) {
        int j0 = jt * 64;
        __syncthreads();
#pragma unroll
        for (int u = 0; u < 2; ++u) {
            int lin = tid + u * 256;
            int r = lin >> 3, c8 = lin & 7;
            const size_t go = (size_t)(bh * 1024 + j0 + r) * 64 + c8 * 8;
            *(uint4*)&KH[r][c8 * 8] = *(const uint4*)(g_k_hi + go);
            *(uint4*)&KL[r][c8 * 8] = *(const uint4*)(g_k_lo + go);
        }
        {
            int jj = tid & 63, qp = tid >> 6;
            const size_t go = (size_t)(bh * 1024 + j0 + jj) * 64 + qp * 16;
#pragma unroll
            for (int u = 0; u < 2; ++u) {
                uint4 vh = *(const uint4*)(g_v_hi + go + u * 8);
                uint4 vl = *(const uint4*)(g_v_lo + go + u * 8);
                const __nv_bfloat16* ph = (const __nv_bfloat16*)&vh;
                const __nv_bfloat16* pl = (const __nv_bfloat16*)&vl;
                int d0 = qp * 16 + u * 8;
#pragma unroll
                for (int i = 0; i < 8; ++i) {
                    VTH[d0 + i][jj] = ph[i];
                    VTL[d0 + i][jj] = pl[i];
                }
            }
        }
        __syncthreads();

        float S[8][4];
#pragma unroll
        for (int nf = 0; nf < 8; ++nf)
#pragma unroll
            for (int e = 0; e < 4; ++e) S[nf][e] = 0.f;
#pragma unroll
        for (int ks = 0; ks < 4; ++ks) {
            uint32_t kb = (uint32_t)ks * 32;
            uint32_t ah[4], al[4];
            ldm_x4(ah, QH_a + q_off + kb);
            ldm_x4(al, QL_a + q_off + kb);
#pragma unroll
            for (int p = 0; p < 4; ++p) {
                uint32_t bh4[4], bl4[4];
                ldm_x4(bh4, KH_a + k_off + (uint32_t)p * (16 * 144) + kb);
                ldm_x4(bl4, KL_a + k_off + (uint32_t)p * (16 * 144) + kb);
                mma16816(S[2 * p],     ah, bh4);
                mma16816(S[2 * p],     ah, bl4);
                mma16816(S[2 * p],     al, bh4);
                mma16816(S[2 * p + 1], ah, bh4 + 2);
                mma16816(S[2 * p + 1], ah, bl4 + 2);
                mma16816(S[2 * p + 1], al, bh4 + 2);
            }
        }

        uint32_t mw[2][2];
        mw[0][0] = mrow0[(j0 >> 5)];     mw[0][1] = mrow0[(j0 >> 5) + 1];
        mw[1][0] = mrow1[(j0 >> 5)];     mw[1][1] = mrow1[(j0 >> 5) + 1];
        float mx0 = -1e30f, mx1 = -1e30f;
#pragma unroll
        for (int nf = 0; nf < 8; ++nf) {
#pragma unroll
            for (int e = 0; e < 4; ++e) {
                int rl_ = rbase + ((e >> 1) << 3);
                int jloc = nf * 8 + 2 * tq + (e & 1);
                float s = S[nf][e];
                int d = (j0 + jloc) - (i0 + rl_);
                if ((unsigned)(d + 4) <= 8u) s += RLS[rl_][d + 4];
                if (((mw[e >> 1][nf >> 2] >> (jloc & 31)) & 1u) == 0u) s = 1e-4f;
                S[nf][e] = s;
                if (e < 2) mx0 = fmaxf(mx0, s); else mx1 = fmaxf(mx1, s);
            }
        }
        mx0 = fmaxf(mx0, __shfl_xor_sync(0xffffffffu, mx0, 1));
        mx0 = fmaxf(mx0, __shfl_xor_sync(0xffffffffu, mx0, 2));
        mx1 = fmaxf(mx1, __shfl_xor_sync(0xffffffffu, mx1, 1));
        mx1 = fmaxf(mx1, __shfl_xor_sync(0xffffffffu, mx1, 2));
        float mn0 = fmaxf(m0, mx0), mn1 = fmaxf(m1, mx1);
        float a0 = __expf(m0 - mn0), a1 = __expf(m1 - mn1);
        m0 = mn0; m1 = mn1;

#pragma unroll
        for (int nd = 0; nd < 8; ++nd) {
            O[nd][0] *= a0; O[nd][1] *= a0; O[nd][2] *= a1; O[nd][3] *= a1;
        }
        if (tq == 0) {
#pragma unroll
            for (int u = 0; u < 9; ++u) {
                BAND[rbase][u] *= a0;
                BAND[rbase + 8][u] *= a1;
            }
        }
        __syncwarp();

        float s0 = 0.f, s1 = 0.f;
#pragma unroll
        for (int nf = 0; nf < 8; ++nf) {
#pragma unroll
            for (int e = 0; e < 4; ++e) {
                float p = __expf(S[nf][e] - ((e < 2) ? mn0 : mn1));
                S[nf][e] = p;
                if (e < 2) s0 += p; else s1 += p;
                int rl_ = rbase + ((e >> 1) << 3);
                int d = (j0 + nf * 8 + 2 * tq + (e & 1)) - (i0 + rl_);
                if ((unsigned)(d + 4) <= 8u) BAND[rl_][d + 4] += p;
            }
        }
        s0 += __shfl_xor_sync(0xffffffffu, s0, 1);
        s0 += __shfl_xor_sync(0xffffffffu, s0, 2);
        s1 += __shfl_xor_sync(0xffffffffu, s1, 1);
        s1 += __shfl_xor_sync(0xffffffffu, s1, 2);
        l0 = l0 * a0 + s0;
        l1 = l1 * a1 + s1;

#pragma unroll
        for (int kj = 0; kj < 4; ++kj) {
            uint32_t aH[4], aL[4];
            split_pack(S[2 * kj][0],     S[2 * kj][1],     aH[0], aL[0]);
            split_pack(S[2 * kj][2],     S[2 * kj][3],     aH[1], aL[1]);
            split_pack(S[2 * kj + 1][0], S[2 * kj + 1][1], aH[2], aL[2]);
            split_pack(S[2 * kj + 1][2], S[2 * kj + 1][3], aH[3], aL[3]);
            uint32_t kb = (uint32_t)kj * 32;
#pragma unroll
            for (int p = 0; p < 4; ++p) {
                uint32_t vh4[4], vl4[4];
                ldm_x4(vh4, VTH_a + k_off + (uint32_t)p * (16 * 144) + kb);
                ldm_x4(vl4, VTL_a + k_off + (uint32_t)p * (16 * 144) + kb);
                mma16816(O[2 * p],     aH, vh4);
                mma16816(O[2 * p],     aH, vl4);
                mma16816(O[2 * p],     aL, vh4);
                mma16816(O[2 * p + 1], aH, vh4 + 2);
                mma16816(O[2 * p + 1], aH, vl4 + 2);
                mma16816(O[2 * p + 1], aL, vh4 + 2);
            }
        }
    }
    __syncwarp();

    float inv0 = 1.f / l0, inv1 = 1.f / l1;
#pragma unroll
    for (int e = 0; e < 4; ++e) {
        int rl_ = rbase + ((e >> 1) << 3);
        float bnd[9];
#pragma unroll
        for (int u = 0; u < 9; ++u) bnd[u] = BAND[rl_][u];
        float inv = (e < 2) ? inv0 : inv1;
        size_t rowbase = ((size_t)(b * 1024 + i0 + rl_)) * 1024 + h * 64;
#pragma unroll
        for (int nd = 0; nd < 8; ++nd) {
            int dcol = nd * 8 + 2 * tq + (e & 1);
            float val = O[nd][e];
#pragma unroll
            for (int u = 0; u < 9; ++u) val += bnd[u] * ERVS[u * 64 + dcol];
            val *= inv;
            __nv_bfloat16 hh, ll;
            splitbf(val, hh, ll);
            g_att_hi[rowbase + dcol] = hh;
            g_att_lo[rowbase + dcol] = ll;
        }
    }
}

// --------------------------------- launch --------------------------------------
extern "C" void kernel_launch(void* const* d_in, const int* in_sizes, int n_in,
                              void* d_out, int out_size)
{
    const float* x   = (const float*)d_in[0];
    const float* c   = (const float*)d_in[1];
    const int*   msk = (const int*)  d_in[2];
    const float* Wq  = (const float*)d_in[3];
    const float* bq  = (const float*)d_in[4];
    const float* Wk  = (const float*)d_in[5];
    const float* bk  = (const float*)d_in[6];
    const float* Wv  = (const float*)d_in[7];
    const float* bv  = (const float*)d_in[8];
    const float* Wo  = (const float*)d_in[9];
    const float* bo  = (const float*)d_in[10];
    const float* erk = (const float*)d_in[11];
    const float* erv = (const float*)d_in[12];
    float* out = (float*)d_out;

    cudaFuncSetAttribute(gemm_mma, cudaFuncAttributeMaxDynamicSharedMemorySize, GEMM_SMEM);
    cudaFuncSetAttribute(attn_fused, cudaFuncAttributeMaxDynamicSharedMemorySize, ATT_SMEM);

    conv_in<<<4096, 256>>>(x, c, bq, bk, bv, bo);
    conv_w<<<dim3(32, 32, 4), 256>>>(Wq, Wk, Wv, Wo);
    mask_pack<<<8192, 256>>>(msk);
    gemm_mma<<<dim3(8, 16, 3), 512, GEMM_SMEM>>>(0, nullptr);   // Q,K,V
    attn_fused<<<dim3(8, 32), 256, ATT_SMEM>>>(erv, erk);
    gemm_mma<<<dim3(8, 16, 1), 512, GEMM_SMEM>>>(1, out);       // @Wo + bo
}

// round 10
// speedup vs baseline: 1.1619x; 1.1619x over previous
#include <cuda_runtime.h>
#include <cuda_bf16.h>
#include <cuda_fp16.h>
#include <cstdint>

// Problem constants
#define B_   2
#define T_   1024
#define CH_  1024
#define H_   16
#define KC_  64
#define WIN_ 4
#define MROWS (B_ * T_)          // 2048
#define BHT  (B_ * H_ * T_)      // 32768

// ---------------- scratch (static device globals; no allocation) ----------------
// q/k/v for attention: bf16 hi/lo split (attention stays 3-pass bf16)
__device__ __nv_bfloat16 g_q_hi[BHT * KC_];
__device__ __nv_bfloat16 g_q_lo[BHT * KC_];
__device__ __nv_bfloat16 g_k_hi[BHT * KC_];
__device__ __nv_bfloat16 g_k_lo[BHT * KC_];
__device__ __nv_bfloat16 g_v_hi[BHT * KC_];
__device__ __nv_bfloat16 g_v_lo[BHT * KC_];

// projection GEMM operands: fp16 (A split hi/lo, W single-rounded)
__device__ __half gx_hi[MROWS * CH_];
__device__ __half gx_lo[MROWS * CH_];
__device__ __half gc_hi[MROWS * CH_];
__device__ __half gc_lo[MROWS * CH_];
__device__ __half gw[4 * CH_ * CH_];          // W^T concat [q|k|v|o], fp16 single
__device__ __half g_att_hi[MROWS * CH_];      // attention out, fp16 split
__device__ __half g_att_lo[MROWS * CH_];
__device__ float g_bias[4 * CH_];
__device__ uint32_t g_mbits[MROWS * (T_ / 32)];

// ======================= helpers ================================================
__device__ __forceinline__ void mma_bf16(float* c, const uint32_t* a, const uint32_t* b)
{
    asm volatile(
        "mma.sync.aligned.m16n8k16.row.col.f32.bf16.bf16.f32 "
        "{%0,%1,%2,%3}, {%4,%5,%6,%7}, {%8,%9}, {%0,%1,%2,%3};"
        : "+f"(c[0]), "+f"(c[1]), "+f"(c[2]), "+f"(c[3])
        : "r"(a[0]), "r"(a[1]), "r"(a[2]), "r"(a[3]), "r"(b[0]), "r"(b[1]));
}

__device__ __forceinline__ void mma_f16(float* c, const uint32_t* a, const uint32_t* b)
{
    asm volatile(
        "mma.sync.aligned.m16n8k16.row.col.f32.f16.f16.f32 "
        "{%0,%1,%2,%3}, {%4,%5,%6,%7}, {%8,%9}, {%0,%1,%2,%3};"
        : "+f"(c[0]), "+f"(c[1]), "+f"(c[2]), "+f"(c[3])
        : "r"(a[0]), "r"(a[1]), "r"(a[2]), "r"(a[3]), "r"(b[0]), "r"(b[1]));
}

__device__ __forceinline__ void ldm_x4(uint32_t* r, uint32_t addr)
{
    asm volatile(
        "ldmatrix.sync.aligned.m8n8.x4.shared.b16 {%0,%1,%2,%3}, [%4];"
        : "=r"(r[0]), "=r"(r[1]), "=r"(r[2]), "=r"(r[3]) : "r"(addr));
}

__device__ __forceinline__ void splitbf(float x, __nv_bfloat16& h, __nv_bfloat16& l)
{
    h = __float2bfloat16_rn(x);
    l = __float2bfloat16_rn(x - __bfloat162float(h));
}

__device__ __forceinline__ void splitf16(float x, __half& h, __half& l)
{
    h = __float2half_rn(x);
    l = __float2half_rn(x - __half2float(h));
}

__device__ __forceinline__ void split_pack(float x, float y, uint32_t& hi, uint32_t& lo)
{
    __nv_bfloat16 hx, lx, hy, ly;
    splitbf(x, hx, lx); splitbf(y, hy, ly);
    __nv_bfloat162 th = __halves2bfloat162(hx, hy);
    __nv_bfloat162 tl = __halves2bfloat162(lx, ly);
    hi = *reinterpret_cast<uint32_t*>(&th);
    lo = *reinterpret_cast<uint32_t*>(&tl);
}

__device__ __forceinline__ uint32_t smem_u32(const void* p) {
    uint32_t a;
    asm("{ .reg .u64 t; cvta.to.shared.u64 t, %1; cvt.u32.u64 %0, t; }"
        : "=r"(a) : "l"(p));
    return a;
}

__device__ __forceinline__ void cpa16(uint32_t dst, const void* src) {
    asm volatile("cp.async.cg.shared.global [%0], [%1], 16;" :: "r"(dst), "l"(src));
}

// ======================= prep kernels ==========================================
__global__ __launch_bounds__(256) void conv_in(
    const float* __restrict__ x, const float* __restrict__ c,
    const float* __restrict__ bq, const float* __restrict__ bk,
    const float* __restrict__ bv, const float* __restrict__ bo)
{
    int i = blockIdx.x * 256 + threadIdx.x;
    const float4* src;
    __half2 *dh, *dl;
    int j;
    if (i < 524288) {
        src = (const float4*)x; j = i;
        dh = (__half2*)gx_hi; dl = (__half2*)gx_lo;
    } else {
        src = (const float4*)c; j = i - 524288;
        dh = (__half2*)gc_hi; dl = (__half2*)gc_lo;
    }
    float4 v = src[j];
    __half hx, lx, hy, ly, hz, lz, hw, lw;
    splitf16(v.x, hx, lx); splitf16(v.y, hy, ly);
    splitf16(v.z, hz, lz); splitf16(v.w, hw, lw);
    dh[2 * j]     = __halves2half2(hx, hy);
    dh[2 * j + 1] = __halves2half2(hz, hw);
    dl[2 * j]     = __halves2half2(lx, ly);
    dl[2 * j + 1] = __halves2half2(lz, lw);
    if (i < 4096) {
        float b = (i < 1024) ? bq[i] : (i < 2048) ? bk[i - 1024]
                : (i < 3072) ? bv[i - 2048] : bo[i - 3072];
        g_bias[i] = b;
    }
}

__global__ __launch_bounds__(256) void conv_w(
    const float* __restrict__ Wq, const float* __restrict__ Wk,
    const float* __restrict__ Wv, const float* __restrict__ Wo)
{
    __shared__ float tile[32][33];
    int z = blockIdx.z;
    const float* W = (z == 0) ? Wq : (z == 1) ? Wk : (z == 2) ? Wv : Wo;
    int n0 = blockIdx.x * 32, k0 = blockIdx.y * 32;
    int tx = threadIdx.x & 31, ty = threadIdx.x >> 5;
#pragma unroll
    for (int u = 0; u < 4; ++u) {
        int k = k0 + ty + u * 8;
        tile[ty + u * 8][tx] = W[k * 1024 + n0 + tx];
    }
    __syncthreads();
#pragma unroll
    for (int u = 0; u < 4; ++u) {
        int r = ty + u * 8;
        float v = tile[tx][r];
        gw[(z * 1024 + n0 + r) * 1024 + k0 + tx] = __float2half_rn(v);
    }
}

__global__ __launch_bounds__(256) void mask_pack(const int* __restrict__ mask)
{
    int idx = blockIdx.x * 256 + threadIdx.x;
    uint32_t bits = __ballot_sync(0xffffffffu, mask[idx] != 0);
    if ((threadIdx.x & 31) == 0) g_mbits[idx >> 5] = bits;
}

// ======================= fp16 2-pass cp.async GEMM =============================
// 256 threads, 2x4 warp grid, 64x32 warp tiles. Stage = Ah|Al|W (3 tiles).
#define LDK 72                        // padded k-stride (fp16), 144B rows
#define TILE_B (128 * LDK * 2)        // 18432 B
#define STAGE_B (3 * TILE_B)          // 55296 B
#define GEMM_SMEM (2 * STAGE_B)       // 110592 B
__global__ __launch_bounds__(256) void gemm_mma(int mode, float* __restrict__ finalout)
{
    extern __shared__ __half sm[];
    uint32_t sbase = smem_u32(sm);

    int tid = threadIdx.x;
    int wid = tid >> 5, lane = tid & 31;
    int g = lane >> 2, tg = lane & 3;
    int warp_m = wid & 1, warp_n = wid >> 1;
    int z = (mode == 0) ? (int)blockIdx.z : 3;

    const __half *A_hi, *A_lo;
    if (mode == 0) {
        if (z == 0) { A_hi = gx_hi; A_lo = gx_lo; }
        else        { A_hi = gc_hi; A_lo = gc_lo; }
    } else { A_hi = g_att_hi; A_lo = g_att_lo; }
    int arow0 = blockIdx.y * 128;
    int brow0 = z * 1024 + blockIdx.x * 128;

    auto issue_stage = [&](int stage, int k0) {
        const __half* srcs[3] = {A_hi, A_lo, gw};
        int rows0[3] = {arow0, arow0, brow0};
        uint32_t stoff = sbase + (uint32_t)stage * STAGE_B;
#pragma unroll
        for (int arr = 0; arr < 3; ++arr) {
#pragma unroll
            for (int u = 0; u < 4; ++u) {
                int lin = tid + u * 256;          // 0..1023
                int r = lin >> 3, c8 = lin & 7;
                cpa16(stoff + (uint32_t)arr * TILE_B + r * 144 + c8 * 16,
                      srcs[arr] + (size_t)(rows0[arr] + r) * 1024 + k0 + c8 * 8);
            }
        }
        asm volatile("cp.async.commit_group;" ::: "memory");
    };

    float acc[4][4][4];
#pragma unroll
    for (int mi = 0; mi < 4; ++mi)
#pragma unroll
        for (int ni = 0; ni < 4; ++ni)
#pragma unroll
            for (int e = 0; e < 4; ++e) acc[mi][ni][e] = 0.f;

    uint32_t a_off = (uint32_t)((warp_m * 64 + (lane & 15)) * 144 + ((lane >> 4) << 4));
    uint32_t b_off = (uint32_t)((warp_n * 32 + (((lane >> 4) & 1) << 3) + (lane & 7)) * 144
                                + (((lane >> 3) & 1) << 4));

    issue_stage(0, 0);

    for (int s = 0; s < 16; ++s) {
        asm volatile("cp.async.wait_group 0;" ::: "memory");
        __syncthreads();
        if (s + 1 < 16) issue_stage((s + 1) & 1, (s + 1) * 64);

        uint32_t stb = sbase + (uint32_t)(s & 1) * STAGE_B;
        uint32_t aHb = stb, aLb = stb + TILE_B, bWb = stb + 2 * TILE_B;

#pragma unroll
        for (int kk = 0; kk < 4; ++kk) {
            uint32_t kb = (uint32_t)kk * 32;
            uint32_t ah[4][4], al[4][4], bw[2][4];
#pragma unroll
            for (int mi = 0; mi < 4; ++mi) {
                ldm_x4(ah[mi], aHb + a_off + (uint32_t)mi * (16 * 144) + kb);
                ldm_x4(al[mi], aLb + a_off + (uint32_t)mi * (16 * 144) + kb);
            }
#pragma unroll
            for (int p = 0; p < 2; ++p)
                ldm_x4(bw[p], bWb + b_off + (uint32_t)p * (16 * 144) + kb);
#pragma unroll
            for (int mi = 0; mi < 4; ++mi)
#pragma unroll
                for (int ni = 0; ni < 4; ++ni) {
                    const uint32_t* bf = &bw[ni >> 1][(ni & 1) * 2];
                    mma_f16(acc[mi][ni], ah[mi], bf);
                    mma_f16(acc[mi][ni], al[mi], bf);
                }
        }
    }

    float scale = (mode == 0 && z == 0) ? 0.125f : 1.0f;
    __nv_bfloat16* dsth = (z == 0) ? g_q_hi : (z == 1) ? g_k_hi : g_v_hi;
    __nv_bfloat16* dstl = (z == 0) ? g_q_lo : (z == 1) ? g_k_lo : g_v_lo;
#pragma unroll
    for (int mi = 0; mi < 4; ++mi) {
#pragma unroll
        for (int ni = 0; ni < 4; ++ni) {
#pragma unroll
            for (int e = 0; e < 4; ++e) {
                int row = blockIdx.y * 128 + warp_m * 64 + mi * 16 + g + ((e >> 1) ? 8 : 0);
                int col = blockIdx.x * 128 + warp_n * 32 + ni * 8 + 2 * tg + (e & 1);
                float v = (acc[mi][ni][e] + g_bias[z * 1024 + col]) * scale;
                if (mode == 0) {
                    int h = col >> 6, bb = row >> 10, t = row & 1023, d = col & 63;
                    int idx = (((bb * 16 + h) << 16) | (t << 6)) + d;
                    __nv_bfloat16 hh, ll;
                    splitbf(v, hh, ll);
                    dsth[idx] = hh;
                    dstl[idx] = ll;
                } else {
                    finalout[(size_t)row * 1024 + col] = v;
                }
            }
        }
    }
}

// =================== fused flash attention (bf16 3-pass, unchanged) =============
#define ATT_SMEM 89088
__global__ __launch_bounds__(256, 2) void attn_fused(
    const float* __restrict__ erv, const float* __restrict__ erk)
{
    extern __shared__ char smc[];
    __nv_bfloat16 (*QH)[72]  = (__nv_bfloat16(*)[72])(smc);
    __nv_bfloat16 (*QL)[72]  = (__nv_bfloat16(*)[72])(smc + 18432);
    __nv_bfloat16 (*KH)[72]  = (__nv_bfloat16(*)[72])(smc + 36864);
    __nv_bfloat16 (*KL)[72]  = (__nv_bfloat16(*)[72])(smc + 46080);
    __nv_bfloat16 (*VTH)[72] = (__nv_bfloat16(*)[72])(smc + 55296);
    __nv_bfloat16 (*VTL)[72] = (__nv_bfloat16(*)[72])(smc + 64512);
    float (*BAND)[12] = (float(*)[12])(smc + 73728);
    float (*RLS)[9]   = (float(*)[9])(smc + 79872);
    float* ERVS       = (float*)(smc + 84480);
    float* ERKS       = (float*)(smc + 86784);

    uint32_t sb = smem_u32(smc);
    const uint32_t QH_a = sb, QL_a = sb + 18432, KH_a = sb + 36864, KL_a = sb + 46080;
    const uint32_t VTH_a = sb + 55296, VTL_a = sb + 64512;

    int tid = threadIdx.x, wid = tid >> 5, lane = tid & 31;
    int g = lane >> 2, tq = lane & 3;
    int bh = blockIdx.y, b = bh >> 4, h = bh & 15;
    int i0 = blockIdx.x * 128;

    uint32_t q_off = (uint32_t)((wid * 16 + (lane & 15)) * 144 + ((lane >> 4) << 4));
    uint32_t k_off = (uint32_t)(((((lane >> 4) & 1) << 3) + (lane & 7)) * 144
                                + (((lane >> 3) & 1) << 4));

#pragma unroll
    for (int u = 0; u < 4; ++u) {
        int lin = tid + u * 256;
        int r = lin >> 3, c8 = lin & 7;
        const size_t go = (size_t)(bh * 1024 + i0 + r) * 64 + c8 * 8;
        *(uint4*)&QH[r][c8 * 8] = *(const uint4*)(g_q_hi + go);
        *(uint4*)&QL[r][c8 * 8] = *(const uint4*)(g_q_lo + go);
    }
    for (int idx = tid; idx < 576; idx += 256) { ERVS[idx] = erv[idx]; ERKS[idx] = erk[idx]; }
    for (int idx = tid; idx < 128 * 12; idx += 256) ((float*)BAND)[idx] = 0.f;
    __syncthreads();

    for (int idx = tid; idx < 1152; idx += 256) {
        int r = idx / 9, u = idx - r * 9;
        float s = 0.f;
        const float* e = ERKS + u * 64;
#pragma unroll
        for (int d = 0; d < 64; ++d)
            s += (__bfloat162float(QH[r][d]) + __bfloat162float(QL[r][d])) * e[d];
        RLS[r][u] = s;
    }

    float O[8][4];
#pragma unroll
    for (int nd = 0; nd < 8; ++nd)
#pragma unroll
        for (int e = 0; e < 4; ++e) O[nd][e] = 0.f;
    float m0 = -1e30f, m1 = -1e30f, l0 = 0.f, l1 = 0.f;

    const int rbase = wid * 16 + g;
    const uint32_t* mrow0 = g_mbits + ((size_t)(b << 10) + i0 + rbase) * 32;
    const uint32_t* mrow1 = mrow0 + 8 * 32;

    for (int jt = 0; jt < 16; ++jt) {
        int j0 = jt * 64;
        __syncthreads();
#pragma unroll
        for (int u = 0; u < 2; ++u) {
            int lin = tid + u * 256;
            int r = lin >> 3, c8 = lin & 7;
            const size_t go = (size_t)(bh * 1024 + j0 + r) * 64 + c8 * 8;
            *(uint4*)&KH[r][c8 * 8] = *(const uint4*)(g_k_hi + go);
            *(uint4*)&KL[r][c8 * 8] = *(const uint4*)(g_k_lo + go);
        }
        {
            int jj = tid & 63, qp = tid >> 6;
            const size_t go = (size_t)(bh * 1024 + j0 + jj) * 64 + qp * 16;
#pragma unroll
            for (int u = 0; u < 2; ++u) {
                uint4 vh = *(const uint4*)(g_v_hi + go + u * 8);
                uint4 vl = *(const uint4*)(g_v_lo + go + u * 8);
                const __nv_bfloat16* ph = (const __nv_bfloat16*)&vh;
                const __nv_bfloat16* pl = (const __nv_bfloat16*)&vl;
                int d0 = qp * 16 + u * 8;
#pragma unroll
                for (int i = 0; i < 8; ++i) {
                    VTH[d0 + i][jj] = ph[i];
                    VTL[d0 + i][jj] = pl[i];
                }
            }
        }
        __syncthreads();

        float S[8][4];
#pragma unroll
        for (int nf = 0; nf < 8; ++nf)
#pragma unroll
            for (int e = 0; e < 4; ++e) S[nf][e] = 0.f;
#pragma unroll
        for (int ks = 0; ks < 4; ++ks) {
            uint32_t kb = (uint32_t)ks * 32;
            uint32_t ah[4], al[4];
            ldm_x4(ah, QH_a + q_off + kb);
            ldm_x4(al, QL_a + q_off + kb);
#pragma unroll
            for (int p = 0; p < 4; ++p) {
                uint32_t bh4[4], bl4[4];
                ldm_x4(bh4, KH_a + k_off + (uint32_t)p * (16 * 144) + kb);
                ldm_x4(bl4, KL_a + k_off + (uint32_t)p * (16 * 144) + kb);
                mma_bf16(S[2 * p],     ah, bh4);
                mma_bf16(S[2 * p],     ah, bl4);
                mma_bf16(S[2 * p],     al, bh4);
                mma_bf16(S[2 * p + 1], ah, bh4 + 2);
                mma_bf16(S[2 * p + 1], ah, bl4 + 2);
                mma_bf16(S[2 * p + 1], al, bh4 + 2);
            }
        }

        uint32_t mw[2][2];
        mw[0][0] = mrow0[(j0 >> 5)];     mw[0][1] = mrow0[(j0 >> 5) + 1];
        mw[1][0] = mrow1[(j0 >> 5)];     mw[1][1] = mrow1[(j0 >> 5) + 1];
        float mx0 = -1e30f, mx1 = -1e30f;
#pragma unroll
        for (int nf = 0; nf < 8; ++nf) {
#pragma unroll
            for (int e = 0; e < 4; ++e) {
                int rl_ = rbase + ((e >> 1) << 3);
                int jloc = nf * 8 + 2 * tq + (e & 1);
                float s = S[nf][e];
                int d = (j0 + jloc) - (i0 + rl_);
                if ((unsigned)(d + 4) <= 8u) s += RLS[rl_][d + 4];
                if (((mw[e >> 1][nf >> 2] >> (jloc & 31)) & 1u) == 0u) s = 1e-4f;
                S[nf][e] = s;
                if (e < 2) mx0 = fmaxf(mx0, s); else mx1 = fmaxf(mx1, s);
            }
        }
        mx0 = fmaxf(mx0, __shfl_xor_sync(0xffffffffu, mx0, 1));
        mx0 = fmaxf(mx0, __shfl_xor_sync(0xffffffffu, mx0, 2));
        mx1 = fmaxf(mx1, __shfl_xor_sync(0xffffffffu, mx1, 1));
        mx1 = fmaxf(mx1, __shfl_xor_sync(0xffffffffu, mx1, 2));
        float mn0 = fmaxf(m0, mx0), mn1 = fmaxf(m1, mx1);
        float a0 = __expf(m0 - mn0), a1 = __expf(m1 - mn1);
        m0 = mn0; m1 = mn1;

#pragma unroll
        for (int nd = 0; nd < 8; ++nd) {
            O[nd][0] *= a0; O[nd][1] *= a0; O[nd][2] *= a1; O[nd][3] *= a1;
        }
        if (tq == 0) {
#pragma unroll
            for (int u = 0; u < 9; ++u) {
                BAND[rbase][u] *= a0;
                BAND[rbase + 8][u] *= a1;
            }
        }
        __syncwarp();

        float s0 = 0.f, s1 = 0.f;
#pragma unroll
        for (int nf = 0; nf < 8; ++nf) {
#pragma unroll
            for (int e = 0; e < 4; ++e) {
                float p = __expf(S[nf][e] - ((e < 2) ? mn0 : mn1));
                S[nf][e] = p;
                if (e < 2) s0 += p; else s1 += p;
                int rl_ = rbase + ((e >> 1) << 3);
                int d = (j0 + nf * 8 + 2 * tq + (e & 1)) - (i0 + rl_);
                if ((unsigned)(d + 4) <= 8u) BAND[rl_][d + 4] += p;
            }
        }
        s0 += __shfl_xor_sync(0xffffffffu, s0, 1);
        s0 += __shfl_xor_sync(0xffffffffu, s0, 2);
        s1 += __shfl_xor_sync(0xffffffffu, s1, 1);
        s1 += __shfl_xor_sync(0xffffffffu, s1, 2);
        l0 = l0 * a0 + s0;
        l1 = l1 * a1 + s1;

#pragma unroll
        for (int kj = 0; kj < 4; ++kj) {
            uint32_t aH[4], aL[4];
            split_pack(S[2 * kj][0],     S[2 * kj][1],     aH[0], aL[0]);
            split_pack(S[2 * kj][2],     S[2 * kj][3],     aH[1], aL[1]);
            split_pack(S[2 * kj + 1][0], S[2 * kj + 1][1], aH[2], aL[2]);
            split_pack(S[2 * kj + 1][2], S[2 * kj + 1][3], aH[3], aL[3]);
            uint32_t kb = (uint32_t)kj * 32;
#pragma unroll
            for (int p = 0; p < 4; ++p) {
                uint32_t vh4[4], vl4[4];
                ldm_x4(vh4, VTH_a + k_off + (uint32_t)p * (16 * 144) + kb);
                ldm_x4(vl4, VTL_a + k_off + (uint32_t)p * (16 * 144) + kb);
                mma_bf16(O[2 * p],     aH, vh4);
                mma_bf16(O[2 * p],     aH, vl4);
                mma_bf16(O[2 * p],     aL, vh4);
                mma_bf16(O[2 * p + 1], aH, vh4 + 2);
                mma_bf16(O[2 * p + 1], aH, vl4 + 2);
                mma_bf16(O[2 * p + 1], aL, vh4 + 2);
            }
        }
    }
    __syncwarp();

    // ---- epilogue: out = (O + band . erv) / l, write fp16-split g_att ----
    float inv0 = 1.f / l0, inv1 = 1.f / l1;
#pragma unroll
    for (int e = 0; e < 4; ++e) {
        int rl_ = rbase + ((e >> 1) << 3);
        float bnd[9];
#pragma unroll
        for (int u = 0; u < 9; ++u) bnd[u] = BAND[rl_][u];
        float inv = (e < 2) ? inv0 : inv1;
        size_t rowbase = ((size_t)(b * 1024 + i0 + rl_)) * 1024 + h * 64;
#pragma unroll
        for (int nd = 0; nd < 8; ++nd) {
            int dcol = nd * 8 + 2 * tq + (e & 1);
            float val = O[nd][e];
#pragma unroll
            for (int u = 0; u < 9; ++u) val += bnd[u] * ERVS[u * 64 + dcol];
            val *= inv;
            __half hh, ll;
            splitf16(val, hh, ll);
            g_att_hi[rowbase + dcol] = hh;
            g_att_lo[rowbase + dcol] = ll;
        }
    }
}

// --------------------------------- launch --------------------------------------
extern "C" void kernel_launch(void* const* d_in, const int* in_sizes, int n_in,
                              void* d_out, int out_size)
{
    const float* x   = (const float*)d_in[0];
    const float* c   = (const float*)d_in[1];
    const int*   msk = (const int*)  d_in[2];
    const float* Wq  = (const float*)d_in[3];
    const float* bq  = (const float*)d_in[4];
    const float* Wk  = (const float*)d_in[5];
    const float* bk  = (const float*)d_in[6];
    const float* Wv  = (const float*)d_in[7];
    const float* bv  = (const float*)d_in[8];
    const float* Wo  = (const float*)d_in[9];
    const float* bo  = (const float*)d_in[10];
    const float* erk = (const float*)d_in[11];
    const float* erv = (const float*)d_in[12];
    float* out = (float*)d_out;

    cudaFuncSetAttribute(gemm_mma, cudaFuncAttributeMaxDynamicSharedMemorySize, GEMM_SMEM);
    cudaFuncSetAttribute(attn_fused, cudaFuncAttributeMaxDynamicSharedMemorySize, ATT_SMEM);

    conv_in<<<4096, 256>>>(x, c, bq, bk, bv, bo);
    conv_w<<<dim3(32, 32, 4), 256>>>(Wq, Wk, Wv, Wo);
    mask_pack<<<8192, 256>>>(msk);
    gemm_mma<<<dim3(8, 16, 3), 256, GEMM_SMEM>>>(0, nullptr);   // Q,K,V
    attn_fused<<<dim3(8, 32), 256, ATT_SMEM>>>(erv, erk);
    gemm_mma<<<dim3(8, 16, 1), 256, GEMM_SMEM>>>(1, out);       // @Wo + bo
}

// round 11
// speedup vs baseline: 1.3701x; 1.1792x over previous
#include <cuda_runtime.h>
#include <cuda_bf16.h>
#include <cuda_fp16.h>
#include <cstdint>

// Problem constants
#define B_   2
#define T_   1024
#define CH_  1024
#define H_   16
#define KC_  64
#define WIN_ 4
#define MROWS (B_ * T_)          // 2048
#define BHT  (B_ * H_ * T_)      // 32768

// ---------------- scratch (static device globals; no allocation) ----------------
// attention operands: Q split fp16 hi/lo; K, V single fp16
__device__ __half g_q_hi[BHT * KC_];
__device__ __half g_q_lo[BHT * KC_];
__device__ __half g_k_f16[BHT * KC_];
__device__ __half g_v_f16[BHT * KC_];

// projection GEMM operands: fp16 (A split hi/lo, W single-rounded)
__device__ __half gx_hi[MROWS * CH_];
__device__ __half gx_lo[MROWS * CH_];
__device__ __half gc_hi[MROWS * CH_];
__device__ __half gc_lo[MROWS * CH_];
__device__ __half gw[4 * CH_ * CH_];          // W^T concat [q|k|v|o], fp16 single
__device__ __half g_att_hi[MROWS * CH_];      // attention out, fp16 split
__device__ __half g_att_lo[MROWS * CH_];
__device__ float g_bias[4 * CH_];
__device__ uint32_t g_mbits[MROWS * (T_ / 32)];

// ======================= helpers ================================================
__device__ __forceinline__ void mma_f16(float* c, const uint32_t* a, const uint32_t* b)
{
    asm volatile(
        "mma.sync.aligned.m16n8k16.row.col.f32.f16.f16.f32 "
        "{%0,%1,%2,%3}, {%4,%5,%6,%7}, {%8,%9}, {%0,%1,%2,%3};"
        : "+f"(c[0]), "+f"(c[1]), "+f"(c[2]), "+f"(c[3])
        : "r"(a[0]), "r"(a[1]), "r"(a[2]), "r"(a[3]), "r"(b[0]), "r"(b[1]));
}

__device__ __forceinline__ void ldm_x4(uint32_t* r, uint32_t addr)
{
    asm volatile(
        "ldmatrix.sync.aligned.m8n8.x4.shared.b16 {%0,%1,%2,%3}, [%4];"
        : "=r"(r[0]), "=r"(r[1]), "=r"(r[2]), "=r"(r[3]) : "r"(addr));
}

__device__ __forceinline__ void splitf16(float x, __half& h, __half& l)
{
    h = __float2half_rn(x);
    l = __float2half_rn(x - __half2float(h));
}

__device__ __forceinline__ uint32_t pack_h2(float x, float y)
{
    __half2 t = __halves2half2(__float2half_rn(x), __float2half_rn(y));
    return *reinterpret_cast<uint32_t*>(&t);
}

__device__ __forceinline__ uint32_t smem_u32(const void* p) {
    uint32_t a;
    asm("{ .reg .u64 t; cvta.to.shared.u64 t, %1; cvt.u32.u64 %0, t; }"
        : "=r"(a) : "l"(p));
    return a;
}

__device__ __forceinline__ void cpa16(uint32_t dst, const void* src) {
    asm volatile("cp.async.cg.shared.global [%0], [%1], 16;" :: "r"(dst), "l"(src));
}

// ======================= prep kernels ==========================================
__global__ __launch_bounds__(256) void conv_in(
    const float* __restrict__ x, const float* __restrict__ c,
    const float* __restrict__ bq, const float* __restrict__ bk,
    const float* __restrict__ bv, const float* __restrict__ bo)
{
    int i = blockIdx.x * 256 + threadIdx.x;
    const float4* src;
    __half2 *dh, *dl;
    int j;
    if (i < 524288) {
        src = (const float4*)x; j = i;
        dh = (__half2*)gx_hi; dl = (__half2*)gx_lo;
    } else {
        src = (const float4*)c; j = i - 524288;
        dh = (__half2*)gc_hi; dl = (__half2*)gc_lo;
    }
    float4 v = src[j];
    __half hx, lx, hy, ly, hz, lz, hw, lw;
    splitf16(v.x, hx, lx); splitf16(v.y, hy, ly);
    splitf16(v.z, hz, lz); splitf16(v.w, hw, lw);
    dh[2 * j]     = __halves2half2(hx, hy);
    dh[2 * j + 1] = __halves2half2(hz, hw);
    dl[2 * j]     = __halves2half2(lx, ly);
    dl[2 * j + 1] = __halves2half2(lz, lw);
    if (i < 4096) {
        float b = (i < 1024) ? bq[i] : (i < 2048) ? bk[i - 1024]
                : (i < 3072) ? bv[i - 2048] : bo[i - 3072];
        g_bias[i] = b;
    }
}

__global__ __launch_bounds__(256) void conv_w(
    const float* __restrict__ Wq, const float* __restrict__ Wk,
    const float* __restrict__ Wv, const float* __restrict__ Wo)
{
    __shared__ float tile[32][33];
    int z = blockIdx.z;
    const float* W = (z == 0) ? Wq : (z == 1) ? Wk : (z == 2) ? Wv : Wo;
    int n0 = blockIdx.x * 32, k0 = blockIdx.y * 32;
    int tx = threadIdx.x & 31, ty = threadIdx.x >> 5;
#pragma unroll
    for (int u = 0; u < 4; ++u) {
        int k = k0 + ty + u * 8;
        tile[ty + u * 8][tx] = W[k * 1024 + n0 + tx];
    }
    __syncthreads();
#pragma unroll
    for (int u = 0; u < 4; ++u) {
        int r = ty + u * 8;
        float v = tile[tx][r];
        gw[(z * 1024 + n0 + r) * 1024 + k0 + tx] = __float2half_rn(v);
    }
}

__global__ __launch_bounds__(256) void mask_pack(const int* __restrict__ mask)
{
    int idx = blockIdx.x * 256 + threadIdx.x;
    uint32_t bits = __ballot_sync(0xffffffffu, mask[idx] != 0);
    if ((threadIdx.x & 31) == 0) g_mbits[idx >> 5] = bits;
}

// ======================= fp16 2-pass cp.async GEMM =============================
#define LDK 72
#define TILE_B (128 * LDK * 2)        // 18432 B
#define STAGE_B (3 * TILE_B)          // 55296 B
#define GEMM_SMEM (2 * STAGE_B)       // 110592 B
__global__ __launch_bounds__(256) void gemm_mma(int mode, float* __restrict__ finalout)
{
    extern __shared__ __half sm[];
    uint32_t sbase = smem_u32(sm);

    int tid = threadIdx.x;
    int wid = tid >> 5, lane = tid & 31;
    int g = lane >> 2, tg = lane & 3;
    int warp_m = wid & 1, warp_n = wid >> 1;
    int z = (mode == 0) ? (int)blockIdx.z : 3;

    const __half *A_hi, *A_lo;
    if (mode == 0) {
        if (z == 0) { A_hi = gx_hi; A_lo = gx_lo; }
        else        { A_hi = gc_hi; A_lo = gc_lo; }
    } else { A_hi = g_att_hi; A_lo = g_att_lo; }
    int arow0 = blockIdx.y * 128;
    int brow0 = z * 1024 + blockIdx.x * 128;

    auto issue_stage = [&](int stage, int k0) {
        const __half* srcs[3] = {A_hi, A_lo, gw};
        int rows0[3] = {arow0, arow0, brow0};
        uint32_t stoff = sbase + (uint32_t)stage * STAGE_B;
#pragma unroll
        for (int arr = 0; arr < 3; ++arr) {
#pragma unroll
            for (int u = 0; u < 4; ++u) {
                int lin = tid + u * 256;
                int r = lin >> 3, c8 = lin & 7;
                cpa16(stoff + (uint32_t)arr * TILE_B + r * 144 + c8 * 16,
                      srcs[arr] + (size_t)(rows0[arr] + r) * 1024 + k0 + c8 * 8);
            }
        }
        asm volatile("cp.async.commit_group;" ::: "memory");
    };

    float acc[4][4][4];
#pragma unroll
    for (int mi = 0; mi < 4; ++mi)
#pragma unroll
        for (int ni = 0; ni < 4; ++ni)
#pragma unroll
            for (int e = 0; e < 4; ++e) acc[mi][ni][e] = 0.f;

    uint32_t a_off = (uint32_t)((warp_m * 64 + (lane & 15)) * 144 + ((lane >> 4) << 4));
    uint32_t b_off = (uint32_t)((warp_n * 32 + (((lane >> 4) & 1) << 3) + (lane & 7)) * 144
                                + (((lane >> 3) & 1) << 4));

    issue_stage(0, 0);

    for (int s = 0; s < 16; ++s) {
        asm volatile("cp.async.wait_group 0;" ::: "memory");
        __syncthreads();
        if (s + 1 < 16) issue_stage((s + 1) & 1, (s + 1) * 64);

        uint32_t stb = sbase + (uint32_t)(s & 1) * STAGE_B;
        uint32_t aHb = stb, aLb = stb + TILE_B, bWb = stb + 2 * TILE_B;

#pragma unroll
        for (int kk = 0; kk < 4; ++kk) {
            uint32_t kb = (uint32_t)kk * 32;
            uint32_t ah[4][4], al[4][4], bw[2][4];
#pragma unroll
            for (int mi = 0; mi < 4; ++mi) {
                ldm_x4(ah[mi], aHb + a_off + (uint32_t)mi * (16 * 144) + kb);
                ldm_x4(al[mi], aLb + a_off + (uint32_t)mi * (16 * 144) + kb);
            }
#pragma unroll
            for (int p = 0; p < 2; ++p)
                ldm_x4(bw[p], bWb + b_off + (uint32_t)p * (16 * 144) + kb);
#pragma unroll
            for (int mi = 0; mi < 4; ++mi)
#pragma unroll
                for (int ni = 0; ni < 4; ++ni) {
                    const uint32_t* bf = &bw[ni >> 1][(ni & 1) * 2];
                    mma_f16(acc[mi][ni], ah[mi], bf);
                    mma_f16(acc[mi][ni], al[mi], bf);
                }
        }
    }

    float scale = (mode == 0 && z == 0) ? 0.125f : 1.0f;
#pragma unroll
    for (int mi = 0; mi < 4; ++mi) {
#pragma unroll
        for (int ni = 0; ni < 4; ++ni) {
#pragma unroll
            for (int e = 0; e < 4; ++e) {
                int row = blockIdx.y * 128 + warp_m * 64 + mi * 16 + g + ((e >> 1) ? 8 : 0);
                int col = blockIdx.x * 128 + warp_n * 32 + ni * 8 + 2 * tg + (e & 1);
                float v = (acc[mi][ni][e] + g_bias[z * 1024 + col]) * scale;
                if (mode == 0) {
                    int h = col >> 6, bb = row >> 10, t = row & 1023, d = col & 63;
                    int idx = (((bb * 16 + h) << 16) | (t << 6)) + d;
                    if (z == 0) {
                        __half hh, ll;
                        splitf16(v, hh, ll);
                        g_q_hi[idx] = hh;
                        g_q_lo[idx] = ll;
                    } else if (z == 1) {
                        g_k_f16[idx] = __float2half_rn(v);
                    } else {
                        g_v_f16[idx] = __float2half_rn(v);
                    }
                } else {
                    finalout[(size_t)row * 1024 + col] = v;
                }
            }
        }
    }
}

// =================== fused flash attention (fp16: QK 2-pass, PV 1-pass) =========
// grid (8, 32), 256 threads, 2 CTAs/SM. i-tile=128, j-tile=64.
// Smem (bytes): QH 0 (18432), QL 18432 (18432), KS 36864 (9216), VT 46080 (9216),
//   BAND 55296 (6144), RLS 61440 (4608), ERVS 66048 (2304), ERKS 68352 (2304)
#define ATT_SMEM 70656
__global__ __launch_bounds__(256, 2) void attn_fused(
    const float* __restrict__ erv, const float* __restrict__ erk)
{
    extern __shared__ char smc[];
    __half (*QH)[72] = (__half(*)[72])(smc);
    __half (*QL)[72] = (__half(*)[72])(smc + 18432);
    __half (*KS)[72] = (__half(*)[72])(smc + 36864);
    __half (*VT)[72] = (__half(*)[72])(smc + 46080);
    float (*BAND)[12] = (float(*)[12])(smc + 55296);
    float (*RLS)[9]   = (float(*)[9])(smc + 61440);
    float* ERVS       = (float*)(smc + 66048);
    float* ERKS       = (float*)(smc + 68352);

    uint32_t sb = smem_u32(smc);
    const uint32_t QH_a = sb, QL_a = sb + 18432, KS_a = sb + 36864, VT_a = sb + 46080;

    int tid = threadIdx.x, wid = tid >> 5, lane = tid & 31;
    int g = lane >> 2, tq = lane & 3;
    int bh = blockIdx.y, b = bh >> 4, h = bh & 15;
    int i0 = blockIdx.x * 128;

    uint32_t q_off = (uint32_t)((wid * 16 + (lane & 15)) * 144 + ((lane >> 4) << 4));
    uint32_t k_off = (uint32_t)(((((lane >> 4) & 1) << 3) + (lane & 7)) * 144
                                + (((lane >> 3) & 1) << 4));

    // ---- load Q tile (pre-split fp16), ERKS/ERVS, zero BAND ----
#pragma unroll
    for (int u = 0; u < 4; ++u) {
        int lin = tid + u * 256;
        int r = lin >> 3, c8 = lin & 7;
        const size_t go = (size_t)(bh * 1024 + i0 + r) * 64 + c8 * 8;
        *(uint4*)&QH[r][c8 * 8] = *(const uint4*)(g_q_hi + go);
        *(uint4*)&QL[r][c8 * 8] = *(const uint4*)(g_q_lo + go);
    }
    for (int idx = tid; idx < 576; idx += 256) { ERVS[idx] = erv[idx]; ERKS[idx] = erk[idx]; }
    for (int idx = tid; idx < 128 * 12; idx += 256) ((float*)BAND)[idx] = 0.f;
    __syncthreads();

    // ---- rel-k logits from resident Q tile (fp32) ----
    for (int idx = tid; idx < 1152; idx += 256) {
        int r = idx / 9, u = idx - r * 9;
        float s = 0.f;
        const float* e = ERKS + u * 64;
#pragma unroll
        for (int d = 0; d < 64; ++d)
            s += (__half2float(QH[r][d]) + __half2float(QL[r][d])) * e[d];
        RLS[r][u] = s;
    }

    float O[8][4];
#pragma unroll
    for (int nd = 0; nd < 8; ++nd)
#pragma unroll
        for (int e = 0; e < 4; ++e) O[nd][e] = 0.f;
    float m0 = -1e30f, m1 = -1e30f, l0 = 0.f, l1 = 0.f;

    const int rbase = wid * 16 + g;
    const uint32_t* mrow0 = g_mbits + ((size_t)(b << 10) + i0 + rbase) * 32;
    const uint32_t* mrow1 = mrow0 + 8 * 32;

    for (int jt = 0; jt < 16; ++jt) {
        int j0 = jt * 64;
        __syncthreads();
        // ---- fill K (single fp16) ----
#pragma unroll
        for (int u = 0; u < 2; ++u) {
            int lin = tid + u * 256;
            int r = lin >> 3, c8 = lin & 7;
            *(uint4*)&KS[r][c8 * 8] =
                *(const uint4*)(g_k_f16 + (size_t)(bh * 1024 + j0 + r) * 64 + c8 * 8);
        }
        // ---- fill V^T (single fp16, transpose on store) ----
        {
            int jj = tid & 63, qp = tid >> 6;
            const size_t go = (size_t)(bh * 1024 + j0 + jj) * 64 + qp * 16;
#pragma unroll
            for (int u = 0; u < 2; ++u) {
                uint4 vv = *(const uint4*)(g_v_f16 + go + u * 8);
                const __half* pv = (const __half*)&vv;
                int d0 = qp * 16 + u * 8;
#pragma unroll
                for (int i = 0; i < 8; ++i) VT[d0 + i][jj] = pv[i];
            }
        }
        __syncthreads();

        // ---- S = Qs K^T (Q split x K single: 2 passes) ----
        float S[8][4];
#pragma unroll
        for (int nf = 0; nf < 8; ++nf)
#pragma unroll
            for (int e = 0; e < 4; ++e) S[nf][e] = 0.f;
#pragma unroll
        for (int ks = 0; ks < 4; ++ks) {
            uint32_t kb = (uint32_t)ks * 32;
            uint32_t ah[4], al[4];
            ldm_x4(ah, QH_a + q_off + kb);
            ldm_x4(al, QL_a + q_off + kb);
#pragma unroll
            for (int p = 0; p < 4; ++p) {
                uint32_t k4[4];
                ldm_x4(k4, KS_a + k_off + (uint32_t)p * (16 * 144) + kb);
                mma_f16(S[2 * p],     ah, k4);
                mma_f16(S[2 * p],     al, k4);
                mma_f16(S[2 * p + 1], ah, k4 + 2);
                mma_f16(S[2 * p + 1], al, k4 + 2);
            }
        }

        // ---- fixup: rel-k band + mask; row max ----
        uint32_t mw[2][2];
        mw[0][0] = mrow0[(j0 >> 5)];     mw[0][1] = mrow0[(j0 >> 5) + 1];
        mw[1][0] = mrow1[(j0 >> 5)];     mw[1][1] = mrow1[(j0 >> 5) + 1];
        float mx0 = -1e30f, mx1 = -1e30f;
#pragma unroll
        for (int nf = 0; nf < 8; ++nf) {
#pragma unroll
            for (int e = 0; e < 4; ++e) {
                int rl_ = rbase + ((e >> 1) << 3);
                int jloc = nf * 8 + 2 * tq + (e & 1);
                float s = S[nf][e];
                int d = (j0 + jloc) - (i0 + rl_);
                if ((unsigned)(d + 4) <= 8u) s += RLS[rl_][d + 4];
                if (((mw[e >> 1][nf >> 2] >> (jloc & 31)) & 1u) == 0u) s = 1e-4f;
                S[nf][e] = s;
                if (e < 2) mx0 = fmaxf(mx0, s); else mx1 = fmaxf(mx1, s);
            }
        }
        mx0 = fmaxf(mx0, __shfl_xor_sync(0xffffffffu, mx0, 1));
        mx0 = fmaxf(mx0, __shfl_xor_sync(0xffffffffu, mx0, 2));
        mx1 = fmaxf(mx1, __shfl_xor_sync(0xffffffffu, mx1, 1));
        mx1 = fmaxf(mx1, __shfl_xor_sync(0xffffffffu, mx1, 2));
        float mn0 = fmaxf(m0, mx0), mn1 = fmaxf(m1, mx1);
        float a0 = __expf(m0 - mn0), a1 = __expf(m1 - mn1);
        m0 = mn0; m1 = mn1;

#pragma unroll
        for (int nd = 0; nd < 8; ++nd) {
            O[nd][0] *= a0; O[nd][1] *= a0; O[nd][2] *= a1; O[nd][3] *= a1;
        }
        if (tq == 0) {
#pragma unroll
            for (int u = 0; u < 9; ++u) {
                BAND[rbase][u] *= a0;
                BAND[rbase + 8][u] *= a1;
            }
        }
        __syncwarp();

        // ---- p = exp(s - m), row sums, band adds (fp32 exact) ----
        float s0 = 0.f, s1 = 0.f;
#pragma unroll
        for (int nf = 0; nf < 8; ++nf) {
#pragma unroll
            for (int e = 0; e < 4; ++e) {
                float p = __expf(S[nf][e] - ((e < 2) ? mn0 : mn1));
                S[nf][e] = p;
                if (e < 2) s0 += p; else s1 += p;
                int rl_ = rbase + ((e >> 1) << 3);
                int d = (j0 + nf * 8 + 2 * tq + (e & 1)) - (i0 + rl_);
                if ((unsigned)(d + 4) <= 8u) BAND[rl_][d + 4] += p;
            }
        }
        s0 += __shfl_xor_sync(0xffffffffu, s0, 1);
        s0 += __shfl_xor_sync(0xffffffffu, s0, 2);
        s1 += __shfl_xor_sync(0xffffffffu, s1, 1);
        s1 += __shfl_xor_sync(0xffffffffu, s1, 2);
        l0 = l0 * a0 + s0;
        l1 = l1 * a1 + s1;

        // ---- O += P V (P single fp16 x V single fp16: 1 pass) ----
#pragma unroll
        for (int kj = 0; kj < 4; ++kj) {
            uint32_t aP[4];
            aP[0] = pack_h2(S[2 * kj][0],     S[2 * kj][1]);
            aP[1] = pack_h2(S[2 * kj][2],     S[2 * kj][3]);
            aP[2] = pack_h2(S[2 * kj + 1][0], S[2 * kj + 1][1]);
            aP[3] = pack_h2(S[2 * kj + 1][2], S[2 * kj + 1][3]);
            uint32_t kb = (uint32_t)kj * 32;
#pragma unroll
            for (int p = 0; p < 4; ++p) {
                uint32_t v4[4];
                ldm_x4(v4, VT_a + k_off + (uint32_t)p * (16 * 144) + kb);
                mma_f16(O[2 * p],     aP, v4);
                mma_f16(O[2 * p + 1], aP, v4 + 2);
            }
        }
    }
    __syncwarp();

    // ---- epilogue: out = (O + band . erv) / l, write fp16-split g_att ----
    float inv0 = 1.f / l0, inv1 = 1.f / l1;
#pragma unroll
    for (int e = 0; e < 4; ++e) {
        int rl_ = rbase + ((e >> 1) << 3);
        float bnd[9];
#pragma unroll
        for (int u = 0; u < 9; ++u) bnd[u] = BAND[rl_][u];
        float inv = (e < 2) ? inv0 : inv1;
        size_t rowbase = ((size_t)(b * 1024 + i0 + rl_)) * 1024 + h * 64;
#pragma unroll
        for (int nd = 0; nd < 8; ++nd) {
            int dcol = nd * 8 + 2 * tq + (e & 1);
            float val = O[nd][e];
#pragma unroll
            for (int u = 0; u < 9; ++u) val += bnd[u] * ERVS[u * 64 + dcol];
            val *= inv;
            __half hh, ll;
            splitf16(val, hh, ll);
            g_att_hi[rowbase + dcol] = hh;
            g_att_lo[rowbase + dcol] = ll;
        }
    }
}

// --------------------------------- launch --------------------------------------
extern "C" void kernel_launch(void* const* d_in, const int* in_sizes, int n_in,
                              void* d_out, int out_size)
{
    const float* x   = (const float*)d_in[0];
    const float* c   = (const float*)d_in[1];
    const int*   msk = (const int*)  d_in[2];
    const float* Wq  = (const float*)d_in[3];
    const float* bq  = (const float*)d_in[4];
    const float* Wk  = (const float*)d_in[5];
    const float* bk  = (const float*)d_in[6];
    const float* Wv  = (const float*)d_in[7];
    const float* bv  = (const float*)d_in[8];
    const float* Wo  = (const float*)d_in[9];
    const float* bo  = (const float*)d_in[10];
    const float* erk = (const float*)d_in[11];
    const float* erv = (const float*)d_in[12];
    float* out = (float*)d_out;

    cudaFuncSetAttribute(gemm_mma, cudaFuncAttributeMaxDynamicSharedMemorySize, GEMM_SMEM);
    cudaFuncSetAttribute(attn_fused, cudaFuncAttributeMaxDynamicSharedMemorySize, ATT_SMEM);

    conv_in<<<4096, 256>>>(x, c, bq, bk, bv, bo);
    conv_w<<<dim3(32, 32, 4), 256>>>(Wq, Wk, Wv, Wo);
    mask_pack<<<8192, 256>>>(msk);
    gemm_mma<<<dim3(8, 16, 3), 256, GEMM_SMEM>>>(0, nullptr);   // Q,K,V
    attn_fused<<<dim3(8, 32), 256, ATT_SMEM>>>(erv, erk);
    gemm_mma<<<dim3(8, 16, 1), 256, GEMM_SMEM>>>(1, out);       // @Wo + bo
}

// round 12
// speedup vs baseline: 1.8966x; 1.3843x over previous
#include <cuda_runtime.h>
#include <cuda_fp16.h>
#include <cstdint>

// Problem constants
#define B_   2
#define T_   1024
#define CH_  1024
#define H_   16
#define KC_  64
#define WIN_ 4
#define MROWS (B_ * T_)          // 2048
#define BHT  (B_ * H_ * T_)      // 32768

// ---------------- scratch (static device globals; no allocation) ----------------
// all operands single fp16 (1 MMA pass everywhere)
__device__ __half g_q[BHT * KC_];             // pre-scaled by 1/sqrt(KC)
__device__ __half g_k[BHT * KC_];
__device__ __half g_v[BHT * KC_];
__device__ __half gx[MROWS * CH_];
__device__ __half gc[MROWS * CH_];
__device__ __half gw[4 * CH_ * CH_];          // W^T concat [q|k|v|o]
__device__ __half g_att[MROWS * CH_];
__device__ float g_bias[4 * CH_];
__device__ uint32_t g_mbits[MROWS * (T_ / 32)];

// ======================= helpers ================================================
__device__ __forceinline__ void mma_f16(float* c, const uint32_t* a, const uint32_t* b)
{
    asm volatile(
        "mma.sync.aligned.m16n8k16.row.col.f32.f16.f16.f32 "
        "{%0,%1,%2,%3}, {%4,%5,%6,%7}, {%8,%9}, {%0,%1,%2,%3};"
        : "+f"(c[0]), "+f"(c[1]), "+f"(c[2]), "+f"(c[3])
        : "r"(a[0]), "r"(a[1]), "r"(a[2]), "r"(a[3]), "r"(b[0]), "r"(b[1]));
}

__device__ __forceinline__ void ldm_x4(uint32_t* r, uint32_t addr)
{
    asm volatile(
        "ldmatrix.sync.aligned.m8n8.x4.shared.b16 {%0,%1,%2,%3}, [%4];"
        : "=r"(r[0]), "=r"(r[1]), "=r"(r[2]), "=r"(r[3]) : "r"(addr));
}

__device__ __forceinline__ uint32_t pack_h2(float x, float y)
{
    __half2 t = __halves2half2(__float2half_rn(x), __float2half_rn(y));
    return *reinterpret_cast<uint32_t*>(&t);
}

__device__ __forceinline__ uint32_t smem_u32(const void* p) {
    uint32_t a;
    asm("{ .reg .u64 t; cvta.to.shared.u64 t, %1; cvt.u32.u64 %0, t; }"
        : "=r"(a) : "l"(p));
    return a;
}

__device__ __forceinline__ void cpa16(uint32_t dst, const void* src) {
    asm volatile("cp.async.cg.shared.global [%0], [%1], 16;" :: "r"(dst), "l"(src));
}

// ======================= prep kernels ==========================================
__global__ __launch_bounds__(256) void conv_in(
    const float* __restrict__ x, const float* __restrict__ c,
    const float* __restrict__ bq, const float* __restrict__ bk,
    const float* __restrict__ bv, const float* __restrict__ bo)
{
    int i = blockIdx.x * 256 + threadIdx.x;   // float4 index over x|c
    const float4* src;
    __half2* dst;
    int j;
    if (i < 524288) { src = (const float4*)x; j = i; dst = (__half2*)gx; }
    else            { src = (const float4*)c; j = i - 524288; dst = (__half2*)gc; }
    float4 v = src[j];
    dst[2 * j]     = __halves2half2(__float2half_rn(v.x), __float2half_rn(v.y));
    dst[2 * j + 1] = __halves2half2(__float2half_rn(v.z), __float2half_rn(v.w));
    if (i < 4096) {
        float b = (i < 1024) ? bq[i] : (i < 2048) ? bk[i - 1024]
                : (i < 3072) ? bv[i - 2048] : bo[i - 3072];
        g_bias[i] = b;
    }
}

__global__ __launch_bounds__(256) void conv_w(
    const float* __restrict__ Wq, const float* __restrict__ Wk,
    const float* __restrict__ Wv, const float* __restrict__ Wo)
{
    __shared__ float tile[32][33];
    int z = blockIdx.z;
    const float* W = (z == 0) ? Wq : (z == 1) ? Wk : (z == 2) ? Wv : Wo;
    int n0 = blockIdx.x * 32, k0 = blockIdx.y * 32;
    int tx = threadIdx.x & 31, ty = threadIdx.x >> 5;
#pragma unroll
    for (int u = 0; u < 4; ++u) {
        int k = k0 + ty + u * 8;
        tile[ty + u * 8][tx] = W[k * 1024 + n0 + tx];
    }
    __syncthreads();
#pragma unroll
    for (int u = 0; u < 4; ++u) {
        int r = ty + u * 8;
        gw[(z * 1024 + n0 + r) * 1024 + k0 + tx] = __float2half_rn(tile[tx][r]);
    }
}

__global__ __launch_bounds__(256) void mask_pack(const int* __restrict__ mask)
{
    int idx = blockIdx.x * 256 + threadIdx.x;
    uint32_t bits = __ballot_sync(0xffffffffu, mask[idx] != 0);
    if ((threadIdx.x & 31) == 0) g_mbits[idx >> 5] = bits;
}

// ======================= fp16 1-pass cp.async GEMM =============================
// 256 threads, 2x4 warps, 64x32 warp tiles. Stage = A|W (2 tiles), 2 CTAs/SM.
#define LDK 72
#define TILE_B (128 * LDK * 2)        // 18432 B
#define STAGE_B (2 * TILE_B)          // 36864 B
#define GEMM_SMEM (2 * STAGE_B)       // 73728 B
__global__ __launch_bounds__(256, 2) void gemm_mma(int mode, float* __restrict__ finalout)
{
    extern __shared__ __half sm[];
    uint32_t sbase = smem_u32(sm);

    int tid = threadIdx.x;
    int wid = tid >> 5, lane = tid & 31;
    int g = lane >> 2, tg = lane & 3;
    int warp_m = wid & 1, warp_n = wid >> 1;
    int z = (mode == 0) ? (int)blockIdx.z : 3;

    const __half* A = (mode == 1) ? g_att : (z == 0) ? gx : gc;
    int arow0 = blockIdx.y * 128;
    int brow0 = z * 1024 + blockIdx.x * 128;

    auto issue_stage = [&](int stage, int k0) {
        const __half* srcs[2] = {A, gw};
        int rows0[2] = {arow0, brow0};
        uint32_t stoff = sbase + (uint32_t)stage * STAGE_B;
#pragma unroll
        for (int arr = 0; arr < 2; ++arr) {
#pragma unroll
            for (int u = 0; u < 4; ++u) {
                int lin = tid + u * 256;          // 0..1023
                int r = lin >> 3, c8 = lin & 7;
                cpa16(stoff + (uint32_t)arr * TILE_B + r * 144 + c8 * 16,
                      srcs[arr] + (size_t)(rows0[arr] + r) * 1024 + k0 + c8 * 8);
            }
        }
        asm volatile("cp.async.commit_group;" ::: "memory");
    };

    float acc[4][4][4];
#pragma unroll
    for (int mi = 0; mi < 4; ++mi)
#pragma unroll
        for (int ni = 0; ni < 4; ++ni)
#pragma unroll
            for (int e = 0; e < 4; ++e) acc[mi][ni][e] = 0.f;

    uint32_t a_off = (uint32_t)((warp_m * 64 + (lane & 15)) * 144 + ((lane >> 4) << 4));
    uint32_t b_off = (uint32_t)((warp_n * 32 + (((lane >> 4) & 1) << 3) + (lane & 7)) * 144
                                + (((lane >> 3) & 1) << 4));

    issue_stage(0, 0);

    for (int s = 0; s < 16; ++s) {
        asm volatile("cp.async.wait_group 0;" ::: "memory");
        __syncthreads();
        if (s + 1 < 16) issue_stage((s + 1) & 1, (s + 1) * 64);

        uint32_t stb = sbase + (uint32_t)(s & 1) * STAGE_B;
        uint32_t aAb = stb, bWb = stb + TILE_B;

#pragma unroll
        for (int kk = 0; kk < 4; ++kk) {
            uint32_t kb = (uint32_t)kk * 32;
            uint32_t av[4][4], bw[2][4];
#pragma unroll
            for (int mi = 0; mi < 4; ++mi)
                ldm_x4(av[mi], aAb + a_off + (uint32_t)mi * (16 * 144) + kb);
#pragma unroll
            for (int p = 0; p < 2; ++p)
                ldm_x4(bw[p], bWb + b_off + (uint32_t)p * (16 * 144) + kb);
#pragma unroll
            for (int mi = 0; mi < 4; ++mi)
#pragma unroll
                for (int ni = 0; ni < 4; ++ni)
                    mma_f16(acc[mi][ni], av[mi], &bw[ni >> 1][(ni & 1) * 2]);
        }
    }

    float scale = (mode == 0 && z == 0) ? 0.125f : 1.0f;
#pragma unroll
    for (int mi = 0; mi < 4; ++mi) {
#pragma unroll
        for (int ni = 0; ni < 4; ++ni) {
#pragma unroll
            for (int e = 0; e < 4; ++e) {
                int row = blockIdx.y * 128 + warp_m * 64 + mi * 16 + g + ((e >> 1) ? 8 : 0);
                int col = blockIdx.x * 128 + warp_n * 32 + ni * 8 + 2 * tg + (e & 1);
                float v = (acc[mi][ni][e] + g_bias[z * 1024 + col]) * scale;
                if (mode == 0) {
                    int h = col >> 6, bb = row >> 10, t = row & 1023, d = col & 63;
                    int idx = (((bb * 16 + h) << 16) | (t << 6)) + d;
                    __half* dstg = (z == 0) ? g_q : (z == 1) ? g_k : g_v;
                    dstg[idx] = __float2half_rn(v);
                } else {
                    finalout[(size_t)row * 1024 + col] = v;
                }
            }
        }
    }
}

// =================== fused flash attention (fp16 single, 1 pass per MMA) ========
// grid (8, 32), 256 threads, 2 CTAs/SM. i-tile=128, j-tile=64.
// Smem: QS 0 (18432), KS 18432 (9216), VT 27648 (9216), BAND 36864 (6144),
//       RLS 43008 (4608), ERVS 47616 (2304), ERKS 49920 (2304) -> 52224
#define ATT_SMEM 52224
__global__ __launch_bounds__(256, 2) void attn_fused(
    const float* __restrict__ erv, const float* __restrict__ erk)
{
    extern __shared__ char smc[];
    __half (*QS)[72] = (__half(*)[72])(smc);
    __half (*KS)[72] = (__half(*)[72])(smc + 18432);
    __half (*VT)[72] = (__half(*)[72])(smc + 27648);
    float (*BAND)[12] = (float(*)[12])(smc + 36864);
    float (*RLS)[9]   = (float(*)[9])(smc + 43008);
    float* ERVS       = (float*)(smc + 47616);
    float* ERKS       = (float*)(smc + 49920);

    uint32_t sb = smem_u32(smc);
    const uint32_t QS_a = sb, KS_a = sb + 18432, VT_a = sb + 27648;

    int tid = threadIdx.x, wid = tid >> 5, lane = tid & 31;
    int g = lane >> 2, tq = lane & 3;
    int bh = blockIdx.y, b = bh >> 4, h = bh & 15;
    int i0 = blockIdx.x * 128;

    uint32_t q_off = (uint32_t)((wid * 16 + (lane & 15)) * 144 + ((lane >> 4) << 4));
    uint32_t k_off = (uint32_t)(((((lane >> 4) & 1) << 3) + (lane & 7)) * 144
                                + (((lane >> 3) & 1) << 4));

    // ---- load Q tile, ERKS/ERVS, zero BAND ----
#pragma unroll
    for (int u = 0; u < 4; ++u) {
        int lin = tid + u * 256;
        int r = lin >> 3, c8 = lin & 7;
        *(uint4*)&QS[r][c8 * 8] =
            *(const uint4*)(g_q + (size_t)(bh * 1024 + i0 + r) * 64 + c8 * 8);
    }
    for (int idx = tid; idx < 576; idx += 256) { ERVS[idx] = erv[idx]; ERKS[idx] = erk[idx]; }
    for (int idx = tid; idx < 128 * 12; idx += 256) ((float*)BAND)[idx] = 0.f;
    __syncthreads();

    // ---- rel-k logits from resident Q tile (fp32) ----
    for (int idx = tid; idx < 1152; idx += 256) {
        int r = idx / 9, u = idx - r * 9;
        float s = 0.f;
        const float* e = ERKS + u * 64;
#pragma unroll
        for (int d = 0; d < 64; ++d)
            s += __half2float(QS[r][d]) * e[d];
        RLS[r][u] = s;
    }

    float O[8][4];
#pragma unroll
    for (int nd = 0; nd < 8; ++nd)
#pragma unroll
        for (int e = 0; e < 4; ++e) O[nd][e] = 0.f;
    float m0 = -1e30f, m1 = -1e30f, l0 = 0.f, l1 = 0.f;

    const int rbase = wid * 16 + g;
    const uint32_t* mrow0 = g_mbits + ((size_t)(b << 10) + i0 + rbase) * 32;
    const uint32_t* mrow1 = mrow0 + 8 * 32;

    for (int jt = 0; jt < 16; ++jt) {
        int j0 = jt * 64;
        __syncthreads();
        // ---- fill K ----
#pragma unroll
        for (int u = 0; u < 2; ++u) {
            int lin = tid + u * 256;
            int r = lin >> 3, c8 = lin & 7;
            *(uint4*)&KS[r][c8 * 8] =
                *(const uint4*)(g_k + (size_t)(bh * 1024 + j0 + r) * 64 + c8 * 8);
        }
        // ---- fill V^T (transpose on store) ----
        {
            int jj = tid & 63, qp = tid >> 6;
            const size_t go = (size_t)(bh * 1024 + j0 + jj) * 64 + qp * 16;
#pragma unroll
            for (int u = 0; u < 2; ++u) {
                uint4 vv = *(const uint4*)(g_v + go + u * 8);
                const __half* pv = (const __half*)&vv;
                int d0 = qp * 16 + u * 8;
#pragma unroll
                for (int i = 0; i < 8; ++i) VT[d0 + i][jj] = pv[i];
            }
        }
        __syncthreads();

        // ---- S = Qs K^T (1 pass) ----
        float S[8][4];
#pragma unroll
        for (int nf = 0; nf < 8; ++nf)
#pragma unroll
            for (int e = 0; e < 4; ++e) S[nf][e] = 0.f;
#pragma unroll
        for (int ks = 0; ks < 4; ++ks) {
            uint32_t kb = (uint32_t)ks * 32;
            uint32_t aq[4];
            ldm_x4(aq, QS_a + q_off + kb);
#pragma unroll
            for (int p = 0; p < 4; ++p) {
                uint32_t k4[4];
                ldm_x4(k4, KS_a + k_off + (uint32_t)p * (16 * 144) + kb);
                mma_f16(S[2 * p],     aq, k4);
                mma_f16(S[2 * p + 1], aq, k4 + 2);
            }
        }

        // ---- fixup: rel-k band + mask; row max ----
        uint32_t mw[2][2];
        mw[0][0] = mrow0[(j0 >> 5)];     mw[0][1] = mrow0[(j0 >> 5) + 1];
        mw[1][0] = mrow1[(j0 >> 5)];     mw[1][1] = mrow1[(j0 >> 5) + 1];
        float mx0 = -1e30f, mx1 = -1e30f;
#pragma unroll
        for (int nf = 0; nf < 8; ++nf) {
#pragma unroll
            for (int e = 0; e < 4; ++e) {
                int rl_ = rbase + ((e >> 1) << 3);
                int jloc = nf * 8 + 2 * tq + (e & 1);
                float s = S[nf][e];
                int d = (j0 + jloc) - (i0 + rl_);
                if ((unsigned)(d + 4) <= 8u) s += RLS[rl_][d + 4];
                if (((mw[e >> 1][nf >> 2] >> (jloc & 31)) & 1u) == 0u) s = 1e-4f;
                S[nf][e] = s;
                if (e < 2) mx0 = fmaxf(mx0, s); else mx1 = fmaxf(mx1, s);
            }
        }
        mx0 = fmaxf(mx0, __shfl_xor_sync(0xffffffffu, mx0, 1));
        mx0 = fmaxf(mx0, __shfl_xor_sync(0xffffffffu, mx0, 2));
        mx1 = fmaxf(mx1, __shfl_xor_sync(0xffffffffu, mx1, 1));
        mx1 = fmaxf(mx1, __shfl_xor_sync(0xffffffffu, mx1, 2));
        float mn0 = fmaxf(m0, mx0), mn1 = fmaxf(m1, mx1);
        float a0 = __expf(m0 - mn0), a1 = __expf(m1 - mn1);
        m0 = mn0; m1 = mn1;

#pragma unroll
        for (int nd = 0; nd < 8; ++nd) {
            O[nd][0] *= a0; O[nd][1] *= a0; O[nd][2] *= a1; O[nd][3] *= a1;
        }
        if (tq == 0) {
#pragma unroll
            for (int u = 0; u < 9; ++u) {
                BAND[rbase][u] *= a0;
                BAND[rbase + 8][u] *= a1;
            }
        }
        __syncwarp();

        // ---- p = exp(s - m), row sums, band adds (fp32 exact) ----
        float s0 = 0.f, s1 = 0.f;
#pragma unroll
        for (int nf = 0; nf < 8; ++nf) {
#pragma unroll
            for (int e = 0; e < 4; ++e) {
                float p = __expf(S[nf][e] - ((e < 2) ? mn0 : mn1));
                S[nf][e] = p;
                if (e < 2) s0 += p; else s1 += p;
                int rl_ = rbase + ((e >> 1) << 3);
                int d = (j0 + nf * 8 + 2 * tq + (e & 1)) - (i0 + rl_);
                if ((unsigned)(d + 4) <= 8u) BAND[rl_][d + 4] += p;
            }
        }
        s0 += __shfl_xor_sync(0xffffffffu, s0, 1);
        s0 += __shfl_xor_sync(0xffffffffu, s0, 2);
        s1 += __shfl_xor_sync(0xffffffffu, s1, 1);
        s1 += __shfl_xor_sync(0xffffffffu, s1, 2);
        l0 = l0 * a0 + s0;
        l1 = l1 * a1 + s1;

        // ---- O += P V (1 pass) ----
#pragma unroll
        for (int kj = 0; kj < 4; ++kj) {
            uint32_t aP[4];
            aP[0] = pack_h2(S[2 * kj][0],     S[2 * kj][1]);
            aP[1] = pack_h2(S[2 * kj][2],     S[2 * kj][3]);
            aP[2] = pack_h2(S[2 * kj + 1][0], S[2 * kj + 1][1]);
            aP[3] = pack_h2(S[2 * kj + 1][2], S[2 * kj + 1][3]);
            uint32_t kb = (uint32_t)kj * 32;
#pragma unroll
            for (int p = 0; p < 4; ++p) {
                uint32_t v4[4];
                ldm_x4(v4, VT_a + k_off + (uint32_t)p * (16 * 144) + kb);
                mma_f16(O[2 * p],     aP, v4);
                mma_f16(O[2 * p + 1], aP, v4 + 2);
            }
        }
    }
    __syncwarp();

    // ---- epilogue: out = (O + band . erv) / l, write fp16 g_att ----
    float inv0 = 1.f / l0, inv1 = 1.f / l1;
#pragma unroll
    for (int e = 0; e < 4; ++e) {
        int rl_ = rbase + ((e >> 1) << 3);
        float bnd[9];
#pragma unroll
        for (int u = 0; u < 9; ++u) bnd[u] = BAND[rl_][u];
        float inv = (e < 2) ? inv0 : inv1;
        size_t rowbase = ((size_t)(b * 1024 + i0 + rl_)) * 1024 + h * 64;
#pragma unroll
        for (int nd = 0; nd < 8; ++nd) {
            int dcol = nd * 8 + 2 * tq + (e & 1);
            float val = O[nd][e];
#pragma unroll
            for (int u = 0; u < 9; ++u) val += bnd[u] * ERVS[u * 64 + dcol];
            g_att[rowbase + dcol] = __float2half_rn(val * inv);
        }
    }
}

// --------------------------------- launch --------------------------------------
extern "C" void kernel_launch(void* const* d_in, const int* in_sizes, int n_in,
                              void* d_out, int out_size)
{
    const float* x   = (const float*)d_in[0];
    const float* c   = (const float*)d_in[1];
    const int*   msk = (const int*)  d_in[2];
    const float* Wq  = (const float*)d_in[3];
    const float* bq  = (const float*)d_in[4];
    const float* Wk  = (const float*)d_in[5];
    const float* bk  = (const float*)d_in[6];
    const float* Wv  = (const float*)d_in[7];
    const float* bv  = (const float*)d_in[8];
    const float* Wo  = (const float*)d_in[9];
    const float* bo  = (const float*)d_in[10];
    const float* erk = (const float*)d_in[11];
    const float* erv = (const float*)d_in[12];
    float* out = (float*)d_out;

    cudaFuncSetAttribute(gemm_mma, cudaFuncAttributeMaxDynamicSharedMemorySize, GEMM_SMEM);
    cudaFuncSetAttribute(attn_fused, cudaFuncAttributeMaxDynamicSharedMemorySize, ATT_SMEM);

    conv_in<<<4096, 256>>>(x, c, bq, bk, bv, bo);
    conv_w<<<dim3(32, 32, 4), 256>>>(Wq, Wk, Wv, Wo);
    mask_pack<<<8192, 256>>>(msk);
    gemm_mma<<<dim3(8, 16, 3), 256, GEMM_SMEM>>>(0, nullptr);   // Q,K,V
    attn_fused<<<dim3(8, 32), 256, ATT_SMEM>>>(erv, erk);
    gemm_mma<<<dim3(8, 16, 1), 256, GEMM_SMEM>>>(1, out);       // @Wo + bo
}

// round 13
// speedup vs baseline: 2.0789x; 1.0961x over previous
#include <cuda_runtime.h>
#include <cuda_fp16.h>
#include <cstdint>

// Problem constants
#define B_   2
#define T_   1024
#define CH_  1024
#define H_   16
#define KC_  64
#define WIN_ 4
#define MROWS (B_ * T_)          // 2048
#define BHT  (B_ * H_ * T_)      // 32768

// ---------------- scratch (static device globals; no allocation) ----------------
__device__ __half g_q[BHT * KC_];             // pre-scaled by 1/sqrt(KC)
__device__ __half g_k[BHT * KC_];
__device__ __half g_v[BHT * KC_];
__device__ __half gx[MROWS * CH_];
__device__ __half gc[MROWS * CH_];
__device__ __half gw[4 * CH_ * CH_];          // W^T concat [q|k|v|o]
__device__ __half g_att[MROWS * CH_];
__device__ float g_bias[4 * CH_];
__device__ uint32_t g_mbits[MROWS * (T_ / 32)];

// ======================= helpers ================================================
__device__ __forceinline__ void mma_f16(float* c, const uint32_t* a, const uint32_t* b)
{
    asm volatile(
        "mma.sync.aligned.m16n8k16.row.col.f32.f16.f16.f32 "
        "{%0,%1,%2,%3}, {%4,%5,%6,%7}, {%8,%9}, {%0,%1,%2,%3};"
        : "+f"(c[0]), "+f"(c[1]), "+f"(c[2]), "+f"(c[3])
        : "r"(a[0]), "r"(a[1]), "r"(a[2]), "r"(a[3]), "r"(b[0]), "r"(b[1]));
}

__device__ __forceinline__ void ldm_x4(uint32_t* r, uint32_t addr)
{
    asm volatile(
        "ldmatrix.sync.aligned.m8n8.x4.shared.b16 {%0,%1,%2,%3}, [%4];"
        : "=r"(r[0]), "=r"(r[1]), "=r"(r[2]), "=r"(r[3]) : "r"(addr));
}

__device__ __forceinline__ void ldm_x4_t(uint32_t* r, uint32_t addr)
{
    asm volatile(
        "ldmatrix.sync.aligned.m8n8.x4.trans.shared.b16 {%0,%1,%2,%3}, [%4];"
        : "=r"(r[0]), "=r"(r[1]), "=r"(r[2]), "=r"(r[3]) : "r"(addr));
}

__device__ __forceinline__ uint32_t pack_h2(float x, float y)
{
    __half2 t = __halves2half2(__float2half_rn(x), __float2half_rn(y));
    return *reinterpret_cast<uint32_t*>(&t);
}

__device__ __forceinline__ uint32_t smem_u32(const void* p) {
    uint32_t a;
    asm("{ .reg .u64 t; cvta.to.shared.u64 t, %1; cvt.u32.u64 %0, t; }"
        : "=r"(a) : "l"(p));
    return a;
}

__device__ __forceinline__ void cpa16(uint32_t dst, const void* src) {
    asm volatile("cp.async.cg.shared.global [%0], [%1], 16;" :: "r"(dst), "l"(src));
}

// ======================= merged prep kernel =====================================
// blocks [0,4096): x|c fp32->fp16 (+bias gather)
// blocks [4096,8192): W transpose + fp16 round
// blocks [8192,16384): mask bit-pack
__global__ __launch_bounds__(256) void prep(
    const float* __restrict__ x, const float* __restrict__ c,
    const int* __restrict__ mask,
    const float* __restrict__ Wq, const float* __restrict__ Wk,
    const float* __restrict__ Wv, const float* __restrict__ Wo,
    const float* __restrict__ bq, const float* __restrict__ bk,
    const float* __restrict__ bv, const float* __restrict__ bo)
{
    __shared__ float tile[32][33];
    int blk = blockIdx.x;
    int tid = threadIdx.x;

    if (blk < 4096) {
        int i = blk * 256 + tid;               // float4 index over x|c
        const float4* src;
        __half2* dst;
        int j;
        if (i < 524288) { src = (const float4*)x; j = i; dst = (__half2*)gx; }
        else            { src = (const float4*)c; j = i - 524288; dst = (__half2*)gc; }
        float4 v = src[j];
        dst[2 * j]     = __halves2half2(__float2half_rn(v.x), __float2half_rn(v.y));
        dst[2 * j + 1] = __halves2half2(__float2half_rn(v.z), __float2half_rn(v.w));
        if (i < 4096) {
            float b = (i < 1024) ? bq[i] : (i < 2048) ? bk[i - 1024]
                    : (i < 3072) ? bv[i - 2048] : bo[i - 3072];
            g_bias[i] = b;
        }
    } else if (blk < 8192) {
        int idx = blk - 4096;
        int z = idx >> 10, within = idx & 1023;
        int n0 = (within & 31) * 32, k0 = (within >> 5) * 32;
        const float* W = (z == 0) ? Wq : (z == 1) ? Wk : (z == 2) ? Wv : Wo;
        int tx = tid & 31, ty = tid >> 5;
#pragma unroll
        for (int u = 0; u < 4; ++u) {
            int k = k0 + ty + u * 8;
            tile[ty + u * 8][tx] = W[k * 1024 + n0 + tx];
        }
        __syncthreads();
#pragma unroll
        for (int u = 0; u < 4; ++u) {
            int r = ty + u * 8;
            gw[(z * 1024 + n0 + r) * 1024 + k0 + tx] = __float2half_rn(tile[tx][r]);
        }
    } else {
        int idx = (blk - 8192) * 256 + tid;
        uint32_t bits = __ballot_sync(0xffffffffu, mask[idx] != 0);
        if ((tid & 31) == 0) g_mbits[idx >> 5] = bits;
    }
}

// ======================= fp16 1-pass cp.async GEMM =============================
#define LDK 72
#define TILE_B (128 * LDK * 2)        // 18432 B
#define STAGE_B (2 * TILE_B)          // 36864 B
#define GEMM_SMEM (2 * STAGE_B)       // 73728 B
__global__ __launch_bounds__(256, 2) void gemm_mma(int mode, float* __restrict__ finalout)
{
    extern __shared__ __half sm[];
    uint32_t sbase = smem_u32(sm);

    int tid = threadIdx.x;
    int wid = tid >> 5, lane = tid & 31;
    int g = lane >> 2, tg = lane & 3;
    int warp_m = wid & 1, warp_n = wid >> 1;
    int z = (mode == 0) ? (int)blockIdx.z : 3;

    const __half* A = (mode == 1) ? g_att : (z == 0) ? gx : gc;
    int arow0 = blockIdx.y * 128;
    int brow0 = z * 1024 + blockIdx.x * 128;

    auto issue_stage = [&](int stage, int k0) {
        const __half* srcs[2] = {A, gw};
        int rows0[2] = {arow0, brow0};
        uint32_t stoff = sbase + (uint32_t)stage * STAGE_B;
#pragma unroll
        for (int arr = 0; arr < 2; ++arr) {
#pragma unroll
            for (int u = 0; u < 4; ++u) {
                int lin = tid + u * 256;
                int r = lin >> 3, c8 = lin & 7;
                cpa16(stoff + (uint32_t)arr * TILE_B + r * 144 + c8 * 16,
                      srcs[arr] + (size_t)(rows0[arr] + r) * 1024 + k0 + c8 * 8);
            }
        }
        asm volatile("cp.async.commit_group;" ::: "memory");
    };

    float acc[4][4][4];
#pragma unroll
    for (int mi = 0; mi < 4; ++mi)
#pragma unroll
        for (int ni = 0; ni < 4; ++ni)
#pragma unroll
            for (int e = 0; e < 4; ++e) acc[mi][ni][e] = 0.f;

    uint32_t a_off = (uint32_t)((warp_m * 64 + (lane & 15)) * 144 + ((lane >> 4) << 4));
    uint32_t b_off = (uint32_t)((warp_n * 32 + (((lane >> 4) & 1) << 3) + (lane & 7)) * 144
                                + (((lane >> 3) & 1) << 4));

    issue_stage(0, 0);

    for (int s = 0; s < 16; ++s) {
        asm volatile("cp.async.wait_group 0;" ::: "memory");
        __syncthreads();
        if (s + 1 < 16) issue_stage((s + 1) & 1, (s + 1) * 64);

        uint32_t stb = sbase + (uint32_t)(s & 1) * STAGE_B;
        uint32_t aAb = stb, bWb = stb + TILE_B;

#pragma unroll
        for (int kk = 0; kk < 4; ++kk) {
            uint32_t kb = (uint32_t)kk * 32;
            uint32_t av[4][4], bw[2][4];
#pragma unroll
            for (int mi = 0; mi < 4; ++mi)
                ldm_x4(av[mi], aAb + a_off + (uint32_t)mi * (16 * 144) + kb);
#pragma unroll
            for (int p = 0; p < 2; ++p)
                ldm_x4(bw[p], bWb + b_off + (uint32_t)p * (16 * 144) + kb);
#pragma unroll
            for (int mi = 0; mi < 4; ++mi)
#pragma unroll
                for (int ni = 0; ni < 4; ++ni)
                    mma_f16(acc[mi][ni], av[mi], &bw[ni >> 1][(ni & 1) * 2]);
        }
    }

    float scale = (mode == 0 && z == 0) ? 0.125f : 1.0f;
#pragma unroll
    for (int mi = 0; mi < 4; ++mi) {
#pragma unroll
        for (int ni = 0; ni < 4; ++ni) {
#pragma unroll
            for (int e = 0; e < 4; ++e) {
                int row = blockIdx.y * 128 + warp_m * 64 + mi * 16 + g + ((e >> 1) ? 8 : 0);
                int col = blockIdx.x * 128 + warp_n * 32 + ni * 8 + 2 * tg + (e & 1);
                float v = (acc[mi][ni][e] + g_bias[z * 1024 + col]) * scale;
                if (mode == 0) {
                    int h = col >> 6, bb = row >> 10, t = row & 1023, d = col & 63;
                    int idx = (((bb * 16 + h) << 16) | (t << 6)) + d;
                    __half* dstg = (z == 0) ? g_q : (z == 1) ? g_k : g_v;
                    dstg[idx] = __float2half_rn(v);
                } else {
                    finalout[(size_t)row * 1024 + col] = v;
                }
            }
        }
    }
}

// =================== fused flash attention (cp.async K/V double-buffer) =========
// grid (8, 32), 256 threads, 2 CTAs/SM. i-tile=128, j-tile=64.
// Smem: QS 0 (18432), K0 18432, K1 27648, V0 36864, V1 46080 (each 9216, [64][72]),
//       BAND 55296 (6144), RLS 61440 (4608), ERVS 66048 (2304), ERKS 68352 (2304)
#define ATT_SMEM 70656
__global__ __launch_bounds__(256, 2) void attn_fused(
    const float* __restrict__ erv, const float* __restrict__ erk)
{
    extern __shared__ char smc[];
    __half (*QS)[72] = (__half(*)[72])(smc);
    float (*BAND)[12] = (float(*)[12])(smc + 55296);
    float (*RLS)[9]   = (float(*)[9])(smc + 61440);
    float* ERVS       = (float*)(smc + 66048);
    float* ERKS       = (float*)(smc + 68352);

    uint32_t sb = smem_u32(smc);
    const uint32_t QS_a = sb;

    int tid = threadIdx.x, wid = tid >> 5, lane = tid & 31;
    int g = lane >> 2, tq = lane & 3;
    int bh = blockIdx.y, b = bh >> 4, h = bh & 15;
    int i0 = blockIdx.x * 128;

    uint32_t q_off = (uint32_t)((wid * 16 + (lane & 15)) * 144 + ((lane >> 4) << 4));
    // K: non-trans B frags (rows = n)
    uint32_t k_off = (uint32_t)(((((lane >> 4) & 1) << 3) + (lane & 7)) * 144
                                + (((lane >> 3) & 1) << 4));
    // V: trans B frags (rows = k = j), V stored [j][d]
    uint32_t v_off = (uint32_t)((lane & 15) * 144 + ((lane >> 4) << 4));

    // cp.async K/V stage loader: 64 rows x 128 B each
    auto issue_kv = [&](int st, int j0) {
        uint32_t kb_ = sb + 18432 + (uint32_t)st * 9216;
        uint32_t vb_ = sb + 36864 + (uint32_t)st * 9216;
#pragma unroll
        for (int u = 0; u < 2; ++u) {
            int lin = tid + u * 256;          // 0..511
            int r = lin >> 3, c8 = lin & 7;
            const size_t go = (size_t)(bh * 1024 + j0 + r) * 64 + c8 * 8;
            cpa16(kb_ + r * 144 + c8 * 16, g_k + go);
            cpa16(vb_ + r * 144 + c8 * 16, g_v + go);
        }
        asm volatile("cp.async.commit_group;" ::: "memory");
    };

    // ---- load Q tile, ERKS/ERVS, zero BAND; prefetch K/V tile 0 ----
#pragma unroll
    for (int u = 0; u < 4; ++u) {
        int lin = tid + u * 256;
        int r = lin >> 3, c8 = lin & 7;
        *(uint4*)&QS[r][c8 * 8] =
            *(const uint4*)(g_q + (size_t)(bh * 1024 + i0 + r) * 64 + c8 * 8);
    }
    for (int idx = tid; idx < 576; idx += 256) { ERVS[idx] = erv[idx]; ERKS[idx] = erk[idx]; }
    for (int idx = tid; idx < 128 * 12; idx += 256) ((float*)BAND)[idx] = 0.f;
    issue_kv(0, 0);
    __syncthreads();

    // ---- rel-k logits from resident Q tile (overlaps K/V tile-0 copy) ----
    for (int idx = tid; idx < 1152; idx += 256) {
        int r = idx / 9, u = idx - r * 9;
        float s = 0.f;
        const float* e = ERKS + u * 64;
#pragma unroll
        for (int d = 0; d < 64; ++d)
            s += __half2float(QS[r][d]) * e[d];
        RLS[r][u] = s;
    }

    float O[8][4];
#pragma unroll
    for (int nd = 0; nd < 8; ++nd)
#pragma unroll
        for (int e = 0; e < 4; ++e) O[nd][e] = 0.f;
    float m0 = -1e30f, m1 = -1e30f, l0 = 0.f, l1 = 0.f;

    const int rbase = wid * 16 + g;
    const uint32_t* mrow0 = g_mbits + ((size_t)(b << 10) + i0 + rbase) * 32;
    const uint32_t* mrow1 = mrow0 + 8 * 32;

    for (int jt = 0; jt < 16; ++jt) {
        int j0 = jt * 64;
        asm volatile("cp.async.wait_group 0;" ::: "memory");
        __syncthreads();                       // buffer (jt&1) ready; also RLS/compute fence
        if (jt + 1 < 16) issue_kv((jt + 1) & 1, (jt + 1) * 64);

        uint32_t KS_a = sb + 18432 + (uint32_t)(jt & 1) * 9216;
        uint32_t VS_a = sb + 36864 + (uint32_t)(jt & 1) * 9216;

        // ---- S = Qs K^T (1 pass) ----
        float S[8][4];
#pragma unroll
        for (int nf = 0; nf < 8; ++nf)
#pragma unroll
            for (int e = 0; e < 4; ++e) S[nf][e] = 0.f;
#pragma unroll
        for (int ks = 0; ks < 4; ++ks) {
            uint32_t kb = (uint32_t)ks * 32;
            uint32_t aq[4];
            ldm_x4(aq, QS_a + q_off + kb);
#pragma unroll
            for (int p = 0; p < 4; ++p) {
                uint32_t k4[4];
                ldm_x4(k4, KS_a + k_off + (uint32_t)p * (16 * 144) + kb);
                mma_f16(S[2 * p],     aq, k4);
                mma_f16(S[2 * p + 1], aq, k4 + 2);
            }
        }

        // ---- fixup: rel-k band + mask; row max ----
        uint32_t mw[2][2];
        mw[0][0] = mrow0[(j0 >> 5)];     mw[0][1] = mrow0[(j0 >> 5) + 1];
        mw[1][0] = mrow1[(j0 >> 5)];     mw[1][1] = mrow1[(j0 >> 5) + 1];
        float mx0 = -1e30f, mx1 = -1e30f;
#pragma unroll
        for (int nf = 0; nf < 8; ++nf) {
#pragma unroll
            for (int e = 0; e < 4; ++e) {
                int rl_ = rbase + ((e >> 1) << 3);
                int jloc = nf * 8 + 2 * tq + (e & 1);
                float s = S[nf][e];
                int d = (j0 + jloc) - (i0 + rl_);
                if ((unsigned)(d + 4) <= 8u) s += RLS[rl_][d + 4];
                if (((mw[e >> 1][nf >> 2] >> (jloc & 31)) & 1u) == 0u) s = 1e-4f;
                S[nf][e] = s;
                if (e < 2) mx0 = fmaxf(mx0, s); else mx1 = fmaxf(mx1, s);
            }
        }
        mx0 = fmaxf(mx0, __shfl_xor_sync(0xffffffffu, mx0, 1));
        mx0 = fmaxf(mx0, __shfl_xor_sync(0xffffffffu, mx0, 2));
        mx1 = fmaxf(mx1, __shfl_xor_sync(0xffffffffu, mx1, 1));
        mx1 = fmaxf(mx1, __shfl_xor_sync(0xffffffffu, mx1, 2));
        float mn0 = fmaxf(m0, mx0), mn1 = fmaxf(m1, mx1);
        float a0 = __expf(m0 - mn0), a1 = __expf(m1 - mn1);
        m0 = mn0; m1 = mn1;

#pragma unroll
        for (int nd = 0; nd < 8; ++nd) {
            O[nd][0] *= a0; O[nd][1] *= a0; O[nd][2] *= a1; O[nd][3] *= a1;
        }
        if (tq == 0) {
#pragma unroll
            for (int u = 0; u < 9; ++u) {
                BAND[rbase][u] *= a0;
                BAND[rbase + 8][u] *= a1;
            }
        }
        __syncwarp();

        // ---- p = exp(s - m), row sums, band adds (fp32 exact) ----
        float s0 = 0.f, s1 = 0.f;
#pragma unroll
        for (int nf = 0; nf < 8; ++nf) {
#pragma unroll
            for (int e = 0; e < 4; ++e) {
                float p = __expf(S[nf][e] - ((e < 2) ? mn0 : mn1));
                S[nf][e] = p;
                if (e < 2) s0 += p; else s1 += p;
                int rl_ = rbase + ((e >> 1) << 3);
                int d = (j0 + nf * 8 + 2 * tq + (e & 1)) - (i0 + rl_);
                if ((unsigned)(d + 4) <= 8u) BAND[rl_][d + 4] += p;
            }
        }
        s0 += __shfl_xor_sync(0xffffffffu, s0, 1);
        s0 += __shfl_xor_sync(0xffffffffu, s0, 2);
        s1 += __shfl_xor_sync(0xffffffffu, s1, 1);
        s1 += __shfl_xor_sync(0xffffffffu, s1, 2);
        l0 = l0 * a0 + s0;
        l1 = l1 * a1 + s1;

        // ---- O += P V (1 pass; V untransposed, ldmatrix.trans frags) ----
#pragma unroll
        for (int kj = 0; kj < 4; ++kj) {
            uint32_t aP[4];
            aP[0] = pack_h2(S[2 * kj][0],     S[2 * kj][1]);
            aP[1] = pack_h2(S[2 * kj][2],     S[2 * kj][3]);
            aP[2] = pack_h2(S[2 * kj + 1][0], S[2 * kj + 1][1]);
            aP[3] = pack_h2(S[2 * kj + 1][2], S[2 * kj + 1][3]);
            uint32_t kjb = (uint32_t)kj * (16 * 144);     // k rows
#pragma unroll
            for (int p = 0; p < 4; ++p) {
                uint32_t v4[4];
                ldm_x4_t(v4, VS_a + v_off + kjb + (uint32_t)p * 32);
                mma_f16(O[2 * p],     aP, v4);
                mma_f16(O[2 * p + 1], aP, v4 + 2);
            }
        }
    }
    __syncwarp();

    // ---- epilogue: out = (O + band . erv) / l, write fp16 g_att ----
    float inv0 = 1.f / l0, inv1 = 1.f / l1;
#pragma unroll
    for (int e = 0; e < 4; ++e) {
        int rl_ = rbase + ((e >> 1) << 3);
        float bnd[9];
#pragma unroll
        for (int u = 0; u < 9; ++u) bnd[u] = BAND[rl_][u];
        float inv = (e < 2) ? inv0 : inv1;
        size_t rowbase = ((size_t)(b * 1024 + i0 + rl_)) * 1024 + h * 64;
#pragma unroll
        for (int nd = 0; nd < 8; ++nd) {
            int dcol = nd * 8 + 2 * tq + (e & 1);
            float val = O[nd][e];
#pragma unroll
            for (int u = 0; u < 9; ++u) val += bnd[u] * ERVS[u * 64 + dcol];
            g_att[rowbase + dcol] = __float2half_rn(val * inv);
        }
    }
}

// --------------------------------- launch --------------------------------------
extern "C" void kernel_launch(void* const* d_in, const int* in_sizes, int n_in,
                              void* d_out, int out_size)
{
    const float* x   = (const float*)d_in[0];
    const float* c   = (const float*)d_in[1];
    const int*   msk = (const int*)  d_in[2];
    const float* Wq  = (const float*)d_in[3];
    const float* bq  = (const float*)d_in[4];
    const float* Wk  = (const float*)d_in[5];
    const float* bk  = (const float*)d_in[6];
    const float* Wv  = (const float*)d_in[7];
    const float* bv  = (const float*)d_in[8];
    const float* Wo  = (const float*)d_in[9];
    const float* bo  = (const float*)d_in[10];
    const float* erk = (const float*)d_in[11];
    const float* erv = (const float*)d_in[12];
    float* out = (float*)d_out;

    cudaFuncSetAttribute(gemm_mma, cudaFuncAttributeMaxDynamicSharedMemorySize, GEMM_SMEM);
    cudaFuncSetAttribute(attn_fused, cudaFuncAttributeMaxDynamicSharedMemorySize, ATT_SMEM);

    prep<<<16384, 256>>>(x, c, msk, Wq, Wk, Wv, Wo, bq, bk, bv, bo);
    gemm_mma<<<dim3(8, 16, 3), 256, GEMM_SMEM>>>(0, nullptr);   // Q,K,V
    attn_fused<<<dim3(8, 32), 256, ATT_SMEM>>>(erv, erk);
    gemm_mma<<<dim3(8, 16, 1), 256, GEMM_SMEM>>>(1, out);       // @Wo + bo
}

// round 14
// speedup vs baseline: 2.1499x; 1.0341x over previous
#include <cuda_runtime.h>
#include <cuda_fp16.h>
#include <cstdint>

// Problem constants
#define B_   2
#define T_   1024
#define CH_  1024
#define H_   16
#define KC_  64
#define WIN_ 4
#define MROWS (B_ * T_)          // 2048
#define BHT  (B_ * H_ * T_)     // 32768

#define LOG2E 1.4426950408889634f

// ---------------- scratch (static device globals; no allocation) ----------------
__device__ __half g_q[BHT * KC_];             // pre-scaled by log2e/sqrt(KC)
__device__ __half g_k[BHT * KC_];
__device__ __half g_v[BHT * KC_];
__device__ __half gx[MROWS * CH_];
__device__ __half gc[MROWS * CH_];
__device__ __half gw[4 * CH_ * CH_];          // W^T concat [q|k|v|o]
__device__ __half g_att[MROWS * CH_];
__device__ float g_bias[4 * CH_];
__device__ uint32_t g_mbits[MROWS * (T_ / 32)];

// ======================= helpers ================================================
__device__ __forceinline__ void mma_f16(float* c, const uint32_t* a, const uint32_t* b)
{
    asm volatile(
        "mma.sync.aligned.m16n8k16.row.col.f32.f16.f16.f32 "
        "{%0,%1,%2,%3}, {%4,%5,%6,%7}, {%8,%9}, {%0,%1,%2,%3};"
        : "+f"(c[0]), "+f"(c[1]), "+f"(c[2]), "+f"(c[3])
        : "r"(a[0]), "r"(a[1]), "r"(a[2]), "r"(a[3]), "r"(b[0]), "r"(b[1]));
}

__device__ __forceinline__ void ldm_x4(uint32_t* r, uint32_t addr)
{
    asm volatile(
        "ldmatrix.sync.aligned.m8n8.x4.shared.b16 {%0,%1,%2,%3}, [%4];"
        : "=r"(r[0]), "=r"(r[1]), "=r"(r[2]), "=r"(r[3]) : "r"(addr));
}

__device__ __forceinline__ void ldm_x4_t(uint32_t* r, uint32_t addr)
{
    asm volatile(
        "ldmatrix.sync.aligned.m8n8.x4.trans.shared.b16 {%0,%1,%2,%3}, [%4];"
        : "=r"(r[0]), "=r"(r[1]), "=r"(r[2]), "=r"(r[3]) : "r"(addr));
}

__device__ __forceinline__ float ex2f(float x)
{
    float y;
    asm("ex2.approx.ftz.f32 %0, %1;" : "=f"(y) : "f"(x));
    return y;
}

__device__ __forceinline__ uint32_t pack_h2(float x, float y)
{
    __half2 t = __halves2half2(__float2half_rn(x), __float2half_rn(y));
    return *reinterpret_cast<uint32_t*>(&t);
}

__device__ __forceinline__ uint32_t smem_u32(const void* p) {
    uint32_t a;
    asm("{ .reg .u64 t; cvta.to.shared.u64 t, %1; cvt.u32.u64 %0, t; }"
        : "=r"(a) : "l"(p));
    return a;
}

__device__ __forceinline__ void cpa16(uint32_t dst, const void* src) {
    asm volatile("cp.async.cg.shared.global [%0], [%1], 16;" :: "r"(dst), "l"(src));
}

// ======================= merged prep kernel =====================================
// blocks [0,4096): x|c fp32->fp16 (+bias gather)
// blocks [4096,8192): W transpose + fp16 round
// blocks [8192,10240): mask bit-pack (int4 + shfl nibble assembly)
__global__ __launch_bounds__(256) void prep(
    const float* __restrict__ x, const float* __restrict__ c,
    const int* __restrict__ mask,
    const float* __restrict__ Wq, const float* __restrict__ Wk,
    const float* __restrict__ Wv, const float* __restrict__ Wo,
    const float* __restrict__ bq, const float* __restrict__ bk,
    const float* __restrict__ bv, const float* __restrict__ bo)
{
    __shared__ float tile[32][33];
    int blk = blockIdx.x;
    int tid = threadIdx.x;

    if (blk < 4096) {
        int i = blk * 256 + tid;               // float4 index over x|c
        const float4* src;
        __half2* dst;
        int j;
        if (i < 524288) { src = (const float4*)x; j = i; dst = (__half2*)gx; }
        else            { src = (const float4*)c; j = i - 524288; dst = (__half2*)gc; }
        float4 v = src[j];
        dst[2 * j]     = __halves2half2(__float2half_rn(v.x), __float2half_rn(v.y));
        dst[2 * j + 1] = __halves2half2(__float2half_rn(v.z), __float2half_rn(v.w));
        if (i < 4096) {
            float b = (i < 1024) ? bq[i] : (i < 2048) ? bk[i - 1024]
                    : (i < 3072) ? bv[i - 2048] : bo[i - 3072];
            g_bias[i] = b;
        }
    } else if (blk < 8192) {
        int idx = blk - 4096;
        int z = idx >> 10, within = idx & 1023;
        int n0 = (within & 31) * 32, k0 = (within >> 5) * 32;
        const float* W = (z == 0) ? Wq : (z == 1) ? Wk : (z == 2) ? Wv : Wo;
        int tx = tid & 31, ty = tid >> 5;
#pragma unroll
        for (int u = 0; u < 4; ++u) {
            int k = k0 + ty + u * 8;
            tile[ty + u * 8][tx] = W[k * 1024 + n0 + tx];
        }
        __syncthreads();
#pragma unroll
        for (int u = 0; u < 4; ++u) {
            int r = ty + u * 8;
            gw[(z * 1024 + n0 + r) * 1024 + k0 + tx] = __float2half_rn(tile[tx][r]);
        }
    } else {
        int idx4 = (blk - 8192) * 256 + tid;   // int4 index
        int4 mv = ((const int4*)mask)[idx4];
        uint32_t v = (uint32_t)(mv.x != 0) | ((uint32_t)(mv.y != 0) << 1)
                   | ((uint32_t)(mv.z != 0) << 2) | ((uint32_t)(mv.w != 0) << 3);
        v |= __shfl_xor_sync(0xffffffffu, v, 1) << 4;
        v |= __shfl_xor_sync(0xffffffffu, v, 2) << 8;
        v |= __shfl_xor_sync(0xffffffffu, v, 4) << 16;
        if ((tid & 7) == 0) g_mbits[idx4 >> 3] = v;
    }
}

// ======================= fp16 1-pass cp.async GEMM =============================
#define LDK 72
#define TILE_B (128 * LDK * 2)        // 18432 B
#define STAGE_B (2 * TILE_B)          // 36864 B
#define GEMM_SMEM (2 * STAGE_B)       // 73728 B
__global__ __launch_bounds__(256, 2) void gemm_mma(int mode, float* __restrict__ finalout)
{
    extern __shared__ __half sm[];
    uint32_t sbase = smem_u32(sm);

    int tid = threadIdx.x;
    int wid = tid >> 5, lane = tid & 31;
    int g = lane >> 2, tg = lane & 3;
    int warp_m = wid & 1, warp_n = wid >> 1;
    int z = (mode == 0) ? (int)blockIdx.z : 3;

    const __half* A = (mode == 1) ? g_att : (z == 0) ? gx : gc;
    int arow0 = blockIdx.y * 128;
    int brow0 = z * 1024 + blockIdx.x * 128;

    auto issue_stage = [&](int stage, int k0) {
        const __half* srcs[2] = {A, gw};
        int rows0[2] = {arow0, brow0};
        uint32_t stoff = sbase + (uint32_t)stage * STAGE_B;
#pragma unroll
        for (int arr = 0; arr < 2; ++arr) {
#pragma unroll
            for (int u = 0; u < 4; ++u) {
                int lin = tid + u * 256;
                int r = lin >> 3, c8 = lin & 7;
                cpa16(stoff + (uint32_t)arr * TILE_B + r * 144 + c8 * 16,
                      srcs[arr] + (size_t)(rows0[arr] + r) * 1024 + k0 + c8 * 8);
            }
        }
        asm volatile("cp.async.commit_group;" ::: "memory");
    };

    float acc[4][4][4];
#pragma unroll
    for (int mi = 0; mi < 4; ++mi)
#pragma unroll
        for (int ni = 0; ni < 4; ++ni)
#pragma unroll
            for (int e = 0; e < 4; ++e) acc[mi][ni][e] = 0.f;

    uint32_t a_off = (uint32_t)((warp_m * 64 + (lane & 15)) * 144 + ((lane >> 4) << 4));
    uint32_t b_off = (uint32_t)((warp_n * 32 + (((lane >> 4) & 1) << 3) + (lane & 7)) * 144
                                + (((lane >> 3) & 1) << 4));

    issue_stage(0, 0);

    for (int s = 0; s < 16; ++s) {
        asm volatile("cp.async.wait_group 0;" ::: "memory");
        __syncthreads();
        if (s + 1 < 16) issue_stage((s + 1) & 1, (s + 1) * 64);

        uint32_t stb = sbase + (uint32_t)(s & 1) * STAGE_B;
        uint32_t aAb = stb, bWb = stb + TILE_B;

#pragma unroll
        for (int kk = 0; kk < 4; ++kk) {
            uint32_t kb = (uint32_t)kk * 32;
            uint32_t av[4][4], bw[2][4];
#pragma unroll
            for (int mi = 0; mi < 4; ++mi)
                ldm_x4(av[mi], aAb + a_off + (uint32_t)mi * (16 * 144) + kb);
#pragma unroll
            for (int p = 0; p < 2; ++p)
                ldm_x4(bw[p], bWb + b_off + (uint32_t)p * (16 * 144) + kb);
#pragma unroll
            for (int mi = 0; mi < 4; ++mi)
#pragma unroll
                for (int ni = 0; ni < 4; ++ni)
                    mma_f16(acc[mi][ni], av[mi], &bw[ni >> 1][(ni & 1) * 2]);
        }
    }

    // q pre-scaled by log2e/8 so attention scores live in log2 units
    float scale = (mode == 0 && z == 0) ? (0.125f * LOG2E) : 1.0f;
#pragma unroll
    for (int mi = 0; mi < 4; ++mi) {
#pragma unroll
        for (int ni = 0; ni < 4; ++ni) {
#pragma unroll
            for (int e = 0; e < 4; ++e) {
                int row = blockIdx.y * 128 + warp_m * 64 + mi * 16 + g + ((e >> 1) ? 8 : 0);
                int col = blockIdx.x * 128 + warp_n * 32 + ni * 8 + 2 * tg + (e & 1);
                float v = (acc[mi][ni][e] + g_bias[z * 1024 + col]) * scale;
                if (mode == 0) {
                    int h = col >> 6, bb = row >> 10, t = row & 1023, d = col & 63;
                    int idx = (((bb * 16 + h) << 16) | (t << 6)) + d;
                    __half* dstg = (z == 0) ? g_q : (z == 1) ? g_k : g_v;
                    dstg[idx] = __float2half_rn(v);
                } else {
                    finalout[(size_t)row * 1024 + col] = v;
                }
            }
        }
    }
}

// =================== fused flash attention (cp.async K/V double-buffer) =========
// grid (8, 32), 256 threads, 2 CTAs/SM. i-tile=128, j-tile=64. Scores in log2 units.
#define ATT_SMEM 70656
#define MASKVAL (1e-4f * LOG2E)
__global__ __launch_bounds__(256, 2) void attn_fused(
    const float* __restrict__ erv, const float* __restrict__ erk)
{
    extern __shared__ char smc[];
    __half (*QS)[72] = (__half(*)[72])(smc);
    float (*BAND)[12] = (float(*)[12])(smc + 55296);
    float (*RLS)[9]   = (float(*)[9])(smc + 61440);
    float* ERVS       = (float*)(smc + 66048);
    float* ERKS       = (float*)(smc + 68352);

    uint32_t sb = smem_u32(smc);
    const uint32_t QS_a = sb;

    int tid = threadIdx.x, wid = tid >> 5, lane = tid & 31;
    int g = lane >> 2, tq = lane & 3;
    int bh = blockIdx.y, b = bh >> 4, h = bh & 15;
    int i0 = blockIdx.x * 128;

    uint32_t q_off = (uint32_t)((wid * 16 + (lane & 15)) * 144 + ((lane >> 4) << 4));
    uint32_t k_off = (uint32_t)(((((lane >> 4) & 1) << 3) + (lane & 7)) * 144
                                + (((lane >> 3) & 1) << 4));
    uint32_t v_off = (uint32_t)((lane & 15) * 144 + ((lane >> 4) << 4));

    auto issue_kv = [&](int st, int j0) {
        uint32_t kb_ = sb + 18432 + (uint32_t)st * 9216;
        uint32_t vb_ = sb + 36864 + (uint32_t)st * 9216;
#pragma unroll
        for (int u = 0; u < 2; ++u) {
            int lin = tid + u * 256;
            int r = lin >> 3, c8 = lin & 7;
            const size_t go = (size_t)(bh * 1024 + j0 + r) * 64 + c8 * 8;
            cpa16(kb_ + r * 144 + c8 * 16, g_k + go);
            cpa16(vb_ + r * 144 + c8 * 16, g_v + go);
        }
        asm volatile("cp.async.commit_group;" ::: "memory");
    };

    // ---- load Q tile, ERKS/ERVS, zero BAND; prefetch K/V tile 0 ----
#pragma unroll
    for (int u = 0; u < 4; ++u) {
        int lin = tid + u * 256;
        int r = lin >> 3, c8 = lin & 7;
        *(uint4*)&QS[r][c8 * 8] =
            *(const uint4*)(g_q + (size_t)(bh * 1024 + i0 + r) * 64 + c8 * 8);
    }
    for (int idx = tid; idx < 576; idx += 256) { ERVS[idx] = erv[idx]; ERKS[idx] = erk[idx]; }
    for (int idx = tid; idx < 128 * 12; idx += 256) ((float*)BAND)[idx] = 0.f;
    issue_kv(0, 0);
    __syncthreads();

    // ---- rel-k logits from resident Q tile (Q carries log2e scale) ----
    for (int idx = tid; idx < 1152; idx += 256) {
        int r = idx / 9, u = idx - r * 9;
        float s = 0.f;
        const float* e = ERKS + u * 64;
#pragma unroll
        for (int d = 0; d < 64; ++d)
            s += __half2float(QS[r][d]) * e[d];
        RLS[r][u] = s;
    }

    float O[8][4];
#pragma unroll
    for (int nd = 0; nd < 8; ++nd)
#pragma unroll
        for (int e = 0; e < 4; ++e) O[nd][e] = 0.f;
    float m0 = -1e30f, m1 = -1e30f, l0 = 0.f, l1 = 0.f;

    const int rbase = wid * 16 + g;
    const uint32_t* mrow0 = g_mbits + ((size_t)(b << 10) + i0 + rbase) * 32;
    const uint32_t* mrow1 = mrow0 + 8 * 32;
    bool bstart = false;

    for (int jt = 0; jt < 16; ++jt) {
        int j0 = jt * 64;
        asm volatile("cp.async.wait_group 0;" ::: "memory");
        __syncthreads();
        if (jt + 1 < 16) issue_kv((jt + 1) & 1, (jt + 1) * 64);

        uint32_t KS_a = sb + 18432 + (uint32_t)(jt & 1) * 9216;
        uint32_t VS_a = sb + 36864 + (uint32_t)(jt & 1) * 9216;

        // rel band intersects this thread's rows only when bp
        bool bp = (j0 + 67 >= i0 + rbase) && (j0 <= i0 + rbase + 12);

        // ---- S = Qs K^T (1 pass) ----
        float S[8][4];
#pragma unroll
        for (int nf = 0; nf < 8; ++nf)
#pragma unroll
            for (int e = 0; e < 4; ++e) S[nf][e] = 0.f;
#pragma unroll
        for (int ks = 0; ks < 4; ++ks) {
            uint32_t kb = (uint32_t)ks * 32;
            uint32_t aq[4];
            ldm_x4(aq, QS_a + q_off + kb);
#pragma unroll
            for (int p = 0; p < 4; ++p) {
                uint32_t k4[4];
                ldm_x4(k4, KS_a + k_off + (uint32_t)p * (16 * 144) + kb);
                mma_f16(S[2 * p],     aq, k4);
                mma_f16(S[2 * p + 1], aq, k4 + 2);
            }
        }

        // ---- fixup: rel-k band (gated) + mask; row max ----
        uint32_t mw[2][2];
        mw[0][0] = mrow0[(j0 >> 5)];     mw[0][1] = mrow0[(j0 >> 5) + 1];
        mw[1][0] = mrow1[(j0 >> 5)];     mw[1][1] = mrow1[(j0 >> 5) + 1];
        float mx0 = -1e30f, mx1 = -1e30f;
#pragma unroll
        for (int nf = 0; nf < 8; ++nf) {
#pragma unroll
            for (int e = 0; e < 4; ++e) {
                int jloc = nf * 8 + 2 * tq + (e & 1);
                float s = S[nf][e];
                if (bp) {
                    int rl_ = rbase + ((e >> 1) << 3);
                    int d = (j0 + jloc) - (i0 + rl_);
                    if ((unsigned)(d + 4) <= 8u) s += RLS[rl_][d + 4];
                }
                if (((mw[e >> 1][nf >> 2] >> (jloc & 31)) & 1u) == 0u) s = MASKVAL;
                S[nf][e] = s;
                if (e < 2) mx0 = fmaxf(mx0, s); else mx1 = fmaxf(mx1, s);
            }
        }
        mx0 = fmaxf(mx0, __shfl_xor_sync(0xffffffffu, mx0, 1));
        mx0 = fmaxf(mx0, __shfl_xor_sync(0xffffffffu, mx0, 2));
        mx1 = fmaxf(mx1, __shfl_xor_sync(0xffffffffu, mx1, 1));
        mx1 = fmaxf(mx1, __shfl_xor_sync(0xffffffffu, mx1, 2));
        float mn0 = fmaxf(m0, mx0), mn1 = fmaxf(m1, mx1);
        float a0 = ex2f(m0 - mn0), a1 = ex2f(m1 - mn1);
        m0 = mn0; m1 = mn1;

#pragma unroll
        for (int nd = 0; nd < 8; ++nd) {
            O[nd][0] *= a0; O[nd][1] *= a0; O[nd][2] *= a1; O[nd][3] *= a1;
        }
        if (bstart && tq == 0) {
#pragma unroll
            for (int u = 0; u < 9; ++u) {
                BAND[rbase][u] *= a0;
                BAND[rbase + 8][u] *= a1;
            }
        }
        bstart = bstart || bp;
        __syncwarp();

        // ---- p = 2^(s - m), row sums, band adds (gated) ----
        float s0 = 0.f, s1 = 0.f;
#pragma unroll
        for (int nf = 0; nf < 8; ++nf) {
#pragma unroll
            for (int e = 0; e < 4; ++e) {
                float p = ex2f(S[nf][e] - ((e < 2) ? mn0 : mn1));
                S[nf][e] = p;
                if (e < 2) s0 += p; else s1 += p;
                if (bp) {
                    int rl_ = rbase + ((e >> 1) << 3);
                    int d = (j0 + nf * 8 + 2 * tq + (e & 1)) - (i0 + rl_);
                    if ((unsigned)(d + 4) <= 8u) BAND[rl_][d + 4] += p;
                }
            }
        }
        s0 += __shfl_xor_sync(0xffffffffu, s0, 1);
        s0 += __shfl_xor_sync(0xffffffffu, s0, 2);
        s1 += __shfl_xor_sync(0xffffffffu, s1, 1);
        s1 += __shfl_xor_sync(0xffffffffu, s1, 2);
        l0 = l0 * a0 + s0;
        l1 = l1 * a1 + s1;

        // ---- O += P V (1 pass; V untransposed, ldmatrix.trans frags) ----
#pragma unroll
        for (int kj = 0; kj < 4; ++kj) {
            uint32_t aP[4];
            aP[0] = pack_h2(S[2 * kj][0],     S[2 * kj][1]);
            aP[1] = pack_h2(S[2 * kj][2],     S[2 * kj][3]);
            aP[2] = pack_h2(S[2 * kj + 1][0], S[2 * kj + 1][1]);
            aP[3] = pack_h2(S[2 * kj + 1][2], S[2 * kj + 1][3]);
            uint32_t kjb = (uint32_t)kj * (16 * 144);
#pragma unroll
            for (int p = 0; p < 4; ++p) {
                uint32_t v4[4];
                ldm_x4_t(v4, VS_a + v_off + kjb + (uint32_t)p * 32);
                mma_f16(O[2 * p],     aP, v4);
                mma_f16(O[2 * p + 1], aP, v4 + 2);
            }
        }
    }
    __syncwarp();

    // ---- epilogue: out = (O + band . erv) / l, write fp16 g_att ----
    float inv0 = 1.f / l0, inv1 = 1.f / l1;
#pragma unroll
    for (int e = 0; e < 4; ++e) {
        int rl_ = rbase + ((e >> 1) << 3);
        float bnd[9];
#pragma unroll
        for (int u = 0; u < 9; ++u) bnd[u] = BAND[rl_][u];
        float inv = (e < 2) ? inv0 : inv1;
        size_t rowbase = ((size_t)(b * 1024 + i0 + rl_)) * 1024 + h * 64;
#pragma unroll
        for (int nd = 0; nd < 8; ++nd) {
            int dcol = nd * 8 + 2 * tq + (e & 1);
            float val = O[nd][e];
#pragma unroll
            for (int u = 0; u < 9; ++u) val += bnd[u] * ERVS[u * 64 + dcol];
            g_att[rowbase + dcol] = __float2half_rn(val * inv);
        }
    }
}

// --------------------------------- launch --------------------------------------
extern "C" void kernel_launch(void* const* d_in, const int* in_sizes, int n_in,
                              void* d_out, int out_size)
{
    const float* x   = (const float*)d_in[0];
    const float* c   = (const float*)d_in[1];
    const int*   msk = (const int*)  d_in[2];
    const float* Wq  = (const float*)d_in[3];
    const float* bq  = (const float*)d_in[4];
    const float* Wk  = (const float*)d_in[5];
    const float* bk  = (const float*)d_in[6];
    const float* Wv  = (const float*)d_in[7];
    const float* bv  = (const float*)d_in[8];
    const float* Wo  = (const float*)d_in[9];
    const float* bo  = (const float*)d_in[10];
    const float* erk = (const float*)d_in[11];
    const float* erv = (const float*)d_in[12];
    float* out = (float*)d_out;

    cudaFuncSetAttribute(gemm_mma, cudaFuncAttributeMaxDynamicSharedMemorySize, GEMM_SMEM);
    cudaFuncSetAttribute(attn_fused, cudaFuncAttributeMaxDynamicSharedMemorySize, ATT_SMEM);

    prep<<<10240, 256>>>(x, c, msk, Wq, Wk, Wv, Wo, bq, bk, bv, bo);
    gemm_mma<<<dim3(8, 16, 3), 256, GEMM_SMEM>>>(0, nullptr);   // Q,K,V
    attn_fused<<<dim3(8, 32), 256, ATT_SMEM>>>(erv, erk);
    gemm_mma<<<dim3(8, 16, 1), 256, GEMM_SMEM>>>(1, out);       // @Wo + bo
}

// round 15
// speedup vs baseline: 2.1531x; 1.0015x over previous
#include <cuda_runtime.h>
#include <cuda_fp16.h>
#include <cstdint>

// Problem constants
#define B_   2
#define T_   1024
#define CH_  1024
#define H_   16
#define KC_  64
#define WIN_ 4
#define MROWS (B_ * T_)          // 2048
#define BHT  (B_ * H_ * T_)     // 32768

#define LOG2E 1.4426950408889634f

// ---------------- scratch (static device globals; no allocation) ----------------
__device__ __half g_q[BHT * KC_];             // pre-scaled by log2e/sqrt(KC)
__device__ __half g_k[BHT * KC_];
__device__ __half g_v[BHT * KC_];
__device__ __half gx[MROWS * CH_];
__device__ __half gc[MROWS * CH_];
__device__ __half gw[4 * CH_ * CH_];          // W^T concat [q|k|v|o]
__device__ __half g_att[MROWS * CH_];
__device__ float g_bias[4 * CH_];
__device__ uint32_t g_mbits[MROWS * (T_ / 32)];

// ======================= helpers ================================================
__device__ __forceinline__ void mma_f16(float* c, const uint32_t* a, const uint32_t* b)
{
    asm volatile(
        "mma.sync.aligned.m16n8k16.row.col.f32.f16.f16.f32 "
        "{%0,%1,%2,%3}, {%4,%5,%6,%7}, {%8,%9}, {%0,%1,%2,%3};"
        : "+f"(c[0]), "+f"(c[1]), "+f"(c[2]), "+f"(c[3])
        : "r"(a[0]), "r"(a[1]), "r"(a[2]), "r"(a[3]), "r"(b[0]), "r"(b[1]));
}

__device__ __forceinline__ void ldm_x4(uint32_t* r, uint32_t addr)
{
    asm volatile(
        "ldmatrix.sync.aligned.m8n8.x4.shared.b16 {%0,%1,%2,%3}, [%4];"
        : "=r"(r[0]), "=r"(r[1]), "=r"(r[2]), "=r"(r[3]) : "r"(addr));
}

__device__ __forceinline__ void ldm_x4_t(uint32_t* r, uint32_t addr)
{
    asm volatile(
        "ldmatrix.sync.aligned.m8n8.x4.trans.shared.b16 {%0,%1,%2,%3}, [%4];"
        : "=r"(r[0]), "=r"(r[1]), "=r"(r[2]), "=r"(r[3]) : "r"(addr));
}

__device__ __forceinline__ float ex2f(float x)
{
    float y;
    asm("ex2.approx.ftz.f32 %0, %1;" : "=f"(y) : "f"(x));
    return y;
}

__device__ __forceinline__ uint32_t pack_h2(float x, float y)
{
    __half2 t = __halves2half2(__float2half_rn(x), __float2half_rn(y));
    return *reinterpret_cast<uint32_t*>(&t);
}

__device__ __forceinline__ uint32_t smem_u32(const void* p) {
    uint32_t a;
    asm("{ .reg .u64 t; cvta.to.shared.u64 t, %1; cvt.u32.u64 %0, t; }"
        : "=r"(a) : "l"(p));
    return a;
}

__device__ __forceinline__ void cpa16(uint32_t dst, const void* src) {
    asm volatile("cp.async.cg.shared.global [%0], [%1], 16;" :: "r"(dst), "l"(src));
}

// ======================= merged prep kernel =====================================
__global__ __launch_bounds__(256) void prep(
    const float* __restrict__ x, const float* __restrict__ c,
    const int* __restrict__ mask,
    const float* __restrict__ Wq, const float* __restrict__ Wk,
    const float* __restrict__ Wv, const float* __restrict__ Wo,
    const float* __restrict__ bq, const float* __restrict__ bk,
    const float* __restrict__ bv, const float* __restrict__ bo)
{
    __shared__ float tile[32][33];
    int blk = blockIdx.x;
    int tid = threadIdx.x;

    if (blk < 4096) {
        int i = blk * 256 + tid;
        const float4* src;
        __half2* dst;
        int j;
        if (i < 524288) { src = (const float4*)x; j = i; dst = (__half2*)gx; }
        else            { src = (const float4*)c; j = i - 524288; dst = (__half2*)gc; }
        float4 v = src[j];
        dst[2 * j]     = __halves2half2(__float2half_rn(v.x), __float2half_rn(v.y));
        dst[2 * j + 1] = __halves2half2(__float2half_rn(v.z), __float2half_rn(v.w));
        if (i < 4096) {
            float b = (i < 1024) ? bq[i] : (i < 2048) ? bk[i - 1024]
                    : (i < 3072) ? bv[i - 2048] : bo[i - 3072];
            g_bias[i] = b;
        }
    } else if (blk < 8192) {
        int idx = blk - 4096;
        int z = idx >> 10, within = idx & 1023;
        int n0 = (within & 31) * 32, k0 = (within >> 5) * 32;
        const float* W = (z == 0) ? Wq : (z == 1) ? Wk : (z == 2) ? Wv : Wo;
        int tx = tid & 31, ty = tid >> 5;
#pragma unroll
        for (int u = 0; u < 4; ++u) {
            int k = k0 + ty + u * 8;
            tile[ty + u * 8][tx] = W[k * 1024 + n0 + tx];
        }
        __syncthreads();
#pragma unroll
        for (int u = 0; u < 4; ++u) {
            int r = ty + u * 8;
            gw[(z * 1024 + n0 + r) * 1024 + k0 + tx] = __float2half_rn(tile[tx][r]);
        }
    } else {
        int idx4 = (blk - 8192) * 256 + tid;
        int4 mv = ((const int4*)mask)[idx4];
        uint32_t v = (uint32_t)(mv.x != 0) | ((uint32_t)(mv.y != 0) << 1)
                   | ((uint32_t)(mv.z != 0) << 2) | ((uint32_t)(mv.w != 0) << 3);
        v |= __shfl_xor_sync(0xffffffffu, v, 1) << 4;
        v |= __shfl_xor_sync(0xffffffffu, v, 2) << 8;
        v |= __shfl_xor_sync(0xffffffffu, v, 4) << 16;
        if ((tid & 7) == 0) g_mbits[idx4 >> 3] = v;
    }
}

// ======================= fp16 1-pass cp.async GEMM =============================
#define LDK 72
#define TILE_B (128 * LDK * 2)        // 18432 B
#define STAGE_B (2 * TILE_B)          // 36864 B
#define GEMM_SMEM (2 * STAGE_B)       // 73728 B
__global__ __launch_bounds__(256, 2) void gemm_mma(int mode, float* __restrict__ finalout)
{
    extern __shared__ __half sm[];
    uint32_t sbase = smem_u32(sm);

    int tid = threadIdx.x;
    int wid = tid >> 5, lane = tid & 31;
    int g = lane >> 2, tg = lane & 3;
    int warp_m = wid & 1, warp_n = wid >> 1;
    int z = (mode == 0) ? (int)blockIdx.z : 3;

    const __half* A = (mode == 1) ? g_att : (z == 0) ? gx : gc;
    int arow0 = blockIdx.y * 128;
    int brow0 = z * 1024 + blockIdx.x * 128;

    auto issue_stage = [&](int stage, int k0) {
        const __half* srcs[2] = {A, gw};
        int rows0[2] = {arow0, brow0};
        uint32_t stoff = sbase + (uint32_t)stage * STAGE_B;
#pragma unroll
        for (int arr = 0; arr < 2; ++arr) {
#pragma unroll
            for (int u = 0; u < 4; ++u) {
                int lin = tid + u * 256;
                int r = lin >> 3, c8 = lin & 7;
                cpa16(stoff + (uint32_t)arr * TILE_B + r * 144 + c8 * 16,
                      srcs[arr] + (size_t)(rows0[arr] + r) * 1024 + k0 + c8 * 8);
            }
        }
        asm volatile("cp.async.commit_group;" ::: "memory");
    };

    float acc[4][4][4];
#pragma unroll
    for (int mi = 0; mi < 4; ++mi)
#pragma unroll
        for (int ni = 0; ni < 4; ++ni)
#pragma unroll
            for (int e = 0; e < 4; ++e) acc[mi][ni][e] = 0.f;

    uint32_t a_off = (uint32_t)((warp_m * 64 + (lane & 15)) * 144 + ((lane >> 4) << 4));
    uint32_t b_off = (uint32_t)((warp_n * 32 + (((lane >> 4) & 1) << 3) + (lane & 7)) * 144
                                + (((lane >> 3) & 1) << 4));

    issue_stage(0, 0);

    for (int s = 0; s < 16; ++s) {
        asm volatile("cp.async.wait_group 0;" ::: "memory");
        __syncthreads();
        if (s + 1 < 16) issue_stage((s + 1) & 1, (s + 1) * 64);

        uint32_t stb = sbase + (uint32_t)(s & 1) * STAGE_B;
        uint32_t aAb = stb, bWb = stb + TILE_B;

#pragma unroll
        for (int kk = 0; kk < 4; ++kk) {
            uint32_t kb = (uint32_t)kk * 32;
            uint32_t av[4][4], bw[2][4];
#pragma unroll
            for (int mi = 0; mi < 4; ++mi)
                ldm_x4(av[mi], aAb + a_off + (uint32_t)mi * (16 * 144) + kb);
#pragma unroll
            for (int p = 0; p < 2; ++p)
                ldm_x4(bw[p], bWb + b_off + (uint32_t)p * (16 * 144) + kb);
#pragma unroll
            for (int mi = 0; mi < 4; ++mi)
#pragma unroll
                for (int ni = 0; ni < 4; ++ni)
                    mma_f16(acc[mi][ni], av[mi], &bw[ni >> 1][(ni & 1) * 2]);
        }
    }

    float scale = (mode == 0 && z == 0) ? (0.125f * LOG2E) : 1.0f;
#pragma unroll
    for (int mi = 0; mi < 4; ++mi) {
#pragma unroll
        for (int ni = 0; ni < 4; ++ni) {
#pragma unroll
            for (int e = 0; e < 4; ++e) {
                int row = blockIdx.y * 128 + warp_m * 64 + mi * 16 + g + ((e >> 1) ? 8 : 0);
                int col = blockIdx.x * 128 + warp_n * 32 + ni * 8 + 2 * tg + (e & 1);
                float v = (acc[mi][ni][e] + g_bias[z * 1024 + col]) * scale;
                if (mode == 0) {
                    int h = col >> 6, bb = row >> 10, t = row & 1023, d = col & 63;
                    int idx = (((bb * 16 + h) << 16) | (t << 6)) + d;
                    __half* dstg = (z == 0) ? g_q : (z == 1) ? g_k : g_v;
                    dstg[idx] = __float2half_rn(v);
                } else {
                    finalout[(size_t)row * 1024 + col] = v;
                }
            }
        }
    }
}

// =================== fused flash attention =======================================
// grid (16, 32), 128 threads (4 warps x 16 rows), 4 CTAs/SM. i-tile=64, j-tile=64.
// Smem: QS 0 (9216), K0 9216, K1 18432, V0 27648, V1 36864 (each 9216),
//       BAND 46080 (3072), RLS 49152 (2304), ERVS 51456 (2304), ERKS 53760 (2304)
#define ATT_SMEM 56064
#define MASKVAL (1e-4f * LOG2E)
__global__ __launch_bounds__(128, 4) void attn_fused(
    const float* __restrict__ erv, const float* __restrict__ erk)
{
    extern __shared__ char smc[];
    __half (*QS)[72] = (__half(*)[72])(smc);
    float (*BAND)[12] = (float(*)[12])(smc + 46080);
    float (*RLS)[9]   = (float(*)[9])(smc + 49152);
    float* ERVS       = (float*)(smc + 51456);
    float* ERKS       = (float*)(smc + 53760);

    uint32_t sb = smem_u32(smc);
    const uint32_t QS_a = sb;

    int tid = threadIdx.x, wid = tid >> 5, lane = tid & 31;
    int g = lane >> 2, tq = lane & 3;
    int bh = blockIdx.y, b = bh >> 4, h = bh & 15;
    int i0 = blockIdx.x * 64;

    uint32_t q_off = (uint32_t)((wid * 16 + (lane & 15)) * 144 + ((lane >> 4) << 4));
    uint32_t k_off = (uint32_t)(((((lane >> 4) & 1) << 3) + (lane & 7)) * 144
                                + (((lane >> 3) & 1) << 4));
    uint32_t v_off = (uint32_t)((lane & 15) * 144 + ((lane >> 4) << 4));

    auto issue_kv = [&](int st, int j0) {
        uint32_t kb_ = sb + 9216 + (uint32_t)st * 9216;
        uint32_t vb_ = sb + 27648 + (uint32_t)st * 9216;
#pragma unroll
        for (int u = 0; u < 4; ++u) {
            int lin = tid + u * 128;          // 0..511
            int r = lin >> 3, c8 = lin & 7;
            const size_t go = (size_t)(bh * 1024 + j0 + r) * 64 + c8 * 8;
            cpa16(kb_ + r * 144 + c8 * 16, g_k + go);
            cpa16(vb_ + r * 144 + c8 * 16, g_v + go);
        }
        asm volatile("cp.async.commit_group;" ::: "memory");
    };

    // ---- load Q tile (64 rows), ERKS/ERVS, zero BAND; prefetch K/V tile 0 ----
#pragma unroll
    for (int u = 0; u < 4; ++u) {
        int lin = tid + u * 128;
        int r = lin >> 3, c8 = lin & 7;
        *(uint4*)&QS[r][c8 * 8] =
            *(const uint4*)(g_q + (size_t)(bh * 1024 + i0 + r) * 64 + c8 * 8);
    }
    for (int idx = tid; idx < 576; idx += 128) { ERVS[idx] = erv[idx]; ERKS[idx] = erk[idx]; }
    for (int idx = tid; idx < 64 * 12; idx += 128) ((float*)BAND)[idx] = 0.f;
    issue_kv(0, 0);
    __syncthreads();

    // ---- rel-k logits from resident Q tile (Q carries log2e scale) ----
    for (int idx = tid; idx < 576; idx += 128) {
        int r = idx / 9, u = idx - r * 9;
        float s = 0.f;
        const float* e = ERKS + u * 64;
#pragma unroll
        for (int d = 0; d < 64; ++d)
            s += __half2float(QS[r][d]) * e[d];
        RLS[r][u] = s;
    }

    float O[8][4];
#pragma unroll
    for (int nd = 0; nd < 8; ++nd)
#pragma unroll
        for (int e = 0; e < 4; ++e) O[nd][e] = 0.f;
    float m0 = -1e30f, m1 = -1e30f, l0 = 0.f, l1 = 0.f;

    const int rbase = wid * 16 + g;                 // 0..63
    const uint32_t* mrow0 = g_mbits + ((size_t)(b << 10) + i0 + rbase) * 32;
    const uint32_t* mrow1 = mrow0 + 8 * 32;
    bool bstart = false;

    for (int jt = 0; jt < 16; ++jt) {
        int j0 = jt * 64;
        asm volatile("cp.async.wait_group 0;" ::: "memory");
        __syncthreads();
        if (jt + 1 < 16) issue_kv((jt + 1) & 1, (jt + 1) * 64);

        uint32_t KS_a = sb + 9216 + (uint32_t)(jt & 1) * 9216;
        uint32_t VS_a = sb + 27648 + (uint32_t)(jt & 1) * 9216;

        bool bp = (j0 + 67 >= i0 + rbase) && (j0 <= i0 + rbase + 12);

        // ---- S = Qs K^T (1 pass) ----
        float S[8][4];
#pragma unroll
        for (int nf = 0; nf < 8; ++nf)
#pragma unroll
            for (int e = 0; e < 4; ++e) S[nf][e] = 0.f;
#pragma unroll
        for (int ks = 0; ks < 4; ++ks) {
            uint32_t kb = (uint32_t)ks * 32;
            uint32_t aq[4];
            ldm_x4(aq, QS_a + q_off + kb);
#pragma unroll
            for (int p = 0; p < 4; ++p) {
                uint32_t k4[4];
                ldm_x4(k4, KS_a + k_off + (uint32_t)p * (16 * 144) + kb);
                mma_f16(S[2 * p],     aq, k4);
                mma_f16(S[2 * p + 1], aq, k4 + 2);
            }
        }

        // ---- fixup: rel-k band (gated) + mask (fast path); row max ----
        uint32_t mw[2][2];
        mw[0][0] = mrow0[(j0 >> 5)];     mw[0][1] = mrow0[(j0 >> 5) + 1];
        mw[1][0] = mrow1[(j0 >> 5)];     mw[1][1] = mrow1[(j0 >> 5) + 1];
        bool allpass = (mw[0][0] & mw[0][1] & mw[1][0] & mw[1][1]) == 0xffffffffu;
        float mx0 = -1e30f, mx1 = -1e30f;
#pragma unroll
        for (int nf = 0; nf < 8; ++nf) {
#pragma unroll
            for (int e = 0; e < 4; ++e) {
                int jloc = nf * 8 + 2 * tq + (e & 1);
                float s = S[nf][e];
                if (bp) {
                    int rl_ = rbase + ((e >> 1) << 3);
                    int d = (j0 + jloc) - (i0 + rl_);
                    if ((unsigned)(d + 4) <= 8u) s += RLS[rl_][d + 4];
                }
                if (!allpass &&
                    ((mw[e >> 1][nf >> 2] >> (jloc & 31)) & 1u) == 0u) s = MASKVAL;
                S[nf][e] = s;
                if (e < 2) mx0 = fmaxf(mx0, s); else mx1 = fmaxf(mx1, s);
            }
        }
        mx0 = fmaxf(mx0, __shfl_xor_sync(0xffffffffu, mx0, 1));
        mx0 = fmaxf(mx0, __shfl_xor_sync(0xffffffffu, mx0, 2));
        mx1 = fmaxf(mx1, __shfl_xor_sync(0xffffffffu, mx1, 1));
        mx1 = fmaxf(mx1, __shfl_xor_sync(0xffffffffu, mx1, 2));
        float mn0 = fmaxf(m0, mx0), mn1 = fmaxf(m1, mx1);
        float a0 = ex2f(m0 - mn0), a1 = ex2f(m1 - mn1);
        m0 = mn0; m1 = mn1;

#pragma unroll
        for (int nd = 0; nd < 8; ++nd) {
            O[nd][0] *= a0; O[nd][1] *= a0; O[nd][2] *= a1; O[nd][3] *= a1;
        }
        if (bstart && tq == 0) {
#pragma unroll
            for (int u = 0; u < 9; ++u) {
                BAND[rbase][u] *= a0;
                BAND[rbase + 8][u] *= a1;
            }
        }
        bstart = bstart || bp;
        __syncwarp();

        // ---- p = 2^(s - m), row sums, band adds (gated) ----
        float s0 = 0.f, s1 = 0.f;
#pragma unroll
        for (int nf = 0; nf < 8; ++nf) {
#pragma unroll
            for (int e = 0; e < 4; ++e) {
                float p = ex2f(S[nf][e] - ((e < 2) ? mn0 : mn1));
                S[nf][e] = p;
                if (e < 2) s0 += p; else s1 += p;
                if (bp) {
                    int rl_ = rbase + ((e >> 1) << 3);
                    int d = (j0 + nf * 8 + 2 * tq + (e & 1)) - (i0 + rl_);
                    if ((unsigned)(d + 4) <= 8u) BAND[rl_][d + 4] += p;
                }
            }
        }
        s0 += __shfl_xor_sync(0xffffffffu, s0, 1);
        s0 += __shfl_xor_sync(0xffffffffu, s0, 2);
        s1 += __shfl_xor_sync(0xffffffffu, s1, 1);
        s1 += __shfl_xor_sync(0xffffffffu, s1, 2);
        l0 = l0 * a0 + s0;
        l1 = l1 * a1 + s1;

        // ---- O += P V (1 pass; V untransposed, ldmatrix.trans frags) ----
#pragma unroll
        for (int kj = 0; kj < 4; ++kj) {
            uint32_t aP[4];
            aP[0] = pack_h2(S[2 * kj][0],     S[2 * kj][1]);
            aP[1] = pack_h2(S[2 * kj][2],     S[2 * kj][3]);
            aP[2] = pack_h2(S[2 * kj + 1][0], S[2 * kj + 1][1]);
            aP[3] = pack_h2(S[2 * kj + 1][2], S[2 * kj + 1][3]);
            uint32_t kjb = (uint32_t)kj * (16 * 144);
#pragma unroll
            for (int p = 0; p < 4; ++p) {
                uint32_t v4[4];
                ldm_x4_t(v4, VS_a + v_off + kjb + (uint32_t)p * 32);
                mma_f16(O[2 * p],     aP, v4);
                mma_f16(O[2 * p + 1], aP, v4 + 2);
            }
        }
    }
    __syncwarp();

    // ---- epilogue: out = (O + band . erv) / l, write fp16 g_att ----
    float inv0 = 1.f / l0, inv1 = 1.f / l1;
#pragma unroll
    for (int e = 0; e < 4; ++e) {
        int rl_ = rbase + ((e >> 1) << 3);
        float bnd[9];
#pragma unroll
        for (int u = 0; u < 9; ++u) bnd[u] = BAND[rl_][u];
        float inv = (e < 2) ? inv0 : inv1;
        size_t rowbase = ((size_t)(b * 1024 + i0 + rl_)) * 1024 + h * 64;
#pragma unroll
        for (int nd = 0; nd < 8; ++nd) {
            int dcol = nd * 8 + 2 * tq + (e & 1);
            float val = O[nd][e];
#pragma unroll
            for (int u = 0; u < 9; ++u) val += bnd[u] * ERVS[u * 64 + dcol];
            g_att[rowbase + dcol] = __float2half_rn(val * inv);
        }
    }
}

// --------------------------------- launch --------------------------------------
extern "C" void kernel_launch(void* const* d_in, const int* in_sizes, int n_in,
                              void* d_out, int out_size)
{
    const float* x   = (const float*)d_in[0];
    const float* c   = (const float*)d_in[1];
    const int*   msk = (const int*)  d_in[2];
    const float* Wq  = (const float*)d_in[3];
    const float* bq  = (const float*)d_in[4];
    const float* Wk  = (const float*)d_in[5];
    const float* bk  = (const float*)d_in[6];
    const float* Wv  = (const float*)d_in[7];
    const float* bv  = (const float*)d_in[8];
    const float* Wo  = (const float*)d_in[9];
    const float* bo  = (const float*)d_in[10];
    const float* erk = (const float*)d_in[11];
    const float* erv = (const float*)d_in[12];
    float* out = (float*)d_out;

    cudaFuncSetAttribute(gemm_mma, cudaFuncAttributeMaxDynamicSharedMemorySize, GEMM_SMEM);
    cudaFuncSetAttribute(attn_fused, cudaFuncAttributeMaxDynamicSharedMemorySize, ATT_SMEM);

    prep<<<10240, 256>>>(x, c, msk, Wq, Wk, Wv, Wo, bq, bk, bv, bo);
    gemm_mma<<<dim3(8, 16, 3), 256, GEMM_SMEM>>>(0, nullptr);   // Q,K,V
    attn_fused<<<dim3(16, 32), 128, ATT_SMEM>>>(erv, erk);      // 16 i-tiles x 32 bh
    gemm_mma<<<dim3(8, 16, 1), 256, GEMM_SMEM>>>(1, out);       // @Wo + bo
}